// round 9
// baseline (speedup 1.0000x reference)
#include <cuda_runtime.h>
#include <cuda_bf16.h>
#include <cstdint>

// ConceptLayer: h = xW+b ; S = decayed scan ; y = bilinear(h,S;C)+h ; LayerNorm
// B=8 T=2048 E=512 H=16 D=32.  sm_100-safe: mma.sync (HMMA), cp.async, ldmatrix.
#define Bn 8
#define Tn 2048
#define En 512
#define Hn 16
#define BT (Bn * Tn)
#define LN_EPS 1e-3f
#define INV_DECAY (1.0f / 1.2f)
#define CHUNK 128
#define NCHUNK (Tn / CHUNK)
#define NCH (Bn * En)
#define WPITCH 520

__device__ float g_h[BT * En];
__device__ float g_S[BT * En];
__device__ float g_y[BT * En];
__device__ float g_local[NCHUNK * NCH];
// C packed split-bf16: [head][n=k*32+i][72 bf16] = [Ch | Cl | pad]
__device__ uint4 g_Cpack[Hn * 1024 * 9];
// W packed transposed split-bf16: [n][k] pitch 520
__device__ __nv_bfloat16 g_Wh[512 * WPITCH];
__device__ __nv_bfloat16 g_Wl[512 * WPITCH];

__device__ __forceinline__ unsigned short bf_hi(float v, float& rem) {
    __nv_bfloat16 h = __float2bfloat16(v);
    rem = v - __bfloat162float(h);
    return __bfloat16_as_ushort(h);
}
__device__ __forceinline__ uint32_t smem_u32(const void* p) {
    uint32_t a;
    asm("{ .reg .u64 t; cvta.to.shared.u64 t, %1; cvt.u32.u64 %0, t; }" : "=r"(a) : "l"(p));
    return a;
}
__device__ __forceinline__ void mma16816(float* d, const uint32_t* a, uint32_t b0, uint32_t b1) {
    asm volatile(
        "mma.sync.aligned.m16n8k16.row.col.f32.bf16.bf16.f32 "
        "{%0,%1,%2,%3}, {%4,%5,%6,%7}, {%8,%9}, {%0,%1,%2,%3};"
        : "+f"(d[0]), "+f"(d[1]), "+f"(d[2]), "+f"(d[3])
        : "r"(a[0]), "r"(a[1]), "r"(a[2]), "r"(a[3]), "r"(b0), "r"(b1));
}
__device__ __forceinline__ void ldsm_x2(uint32_t& r0, uint32_t& r1, uint32_t addr) {
    asm volatile("ldmatrix.sync.aligned.m8n8.x2.shared.b16 {%0,%1}, [%2];"
                 : "=r"(r0), "=r"(r1) : "r"(addr));
}
__device__ __forceinline__ void ldsm_x4(uint32_t* r, uint32_t addr) {
    asm volatile("ldmatrix.sync.aligned.m8n8.x4.shared.b16 {%0,%1,%2,%3}, [%4];"
                 : "=r"(r[0]), "=r"(r[1]), "=r"(r[2]), "=r"(r[3]) : "r"(addr));
}
__device__ __forceinline__ void cp_async16(uint32_t dst, const void* src) {
    asm volatile("cp.async.cg.shared.global [%0], [%1], 16;" :: "r"(dst), "l"(src) : "memory");
}

// ---------------------------------------------------------------------------
// K0a: pack C -> split bf16 [head][n][72]
// ---------------------------------------------------------------------------
__global__ void cpack_kernel(const float* __restrict__ C) {
    const int idx = blockIdx.x * 256 + threadIdx.x;
    const float* src = C + (size_t)idx * 32;
    unsigned short hi[32], lo[32];
#pragma unroll
    for (int j = 0; j < 32; ++j) {
        float r;
        hi[j] = bf_hi(src[j], r);
        lo[j] = __bfloat16_as_ushort(__float2bfloat16(r));
    }
    uint4* dst = g_Cpack + (size_t)idx * 9;
#pragma unroll
    for (int q = 0; q < 4; ++q) {
        uint4 v;
        v.x = (uint32_t)hi[q * 8 + 0] | ((uint32_t)hi[q * 8 + 1] << 16);
        v.y = (uint32_t)hi[q * 8 + 2] | ((uint32_t)hi[q * 8 + 3] << 16);
        v.z = (uint32_t)hi[q * 8 + 4] | ((uint32_t)hi[q * 8 + 5] << 16);
        v.w = (uint32_t)hi[q * 8 + 6] | ((uint32_t)hi[q * 8 + 7] << 16);
        dst[q] = v;
        uint4 w;
        w.x = (uint32_t)lo[q * 8 + 0] | ((uint32_t)lo[q * 8 + 1] << 16);
        w.y = (uint32_t)lo[q * 8 + 2] | ((uint32_t)lo[q * 8 + 3] << 16);
        w.z = (uint32_t)lo[q * 8 + 4] | ((uint32_t)lo[q * 8 + 5] << 16);
        w.w = (uint32_t)lo[q * 8 + 6] | ((uint32_t)lo[q * 8 + 7] << 16);
        dst[4 + q] = w;
    }
}

// ---------------------------------------------------------------------------
// K0b: pack W [k][n] f32 -> g_Wh/g_Wl [n][k] bf16, pitch WPITCH
// ---------------------------------------------------------------------------
__global__ void wpack_kernel(const float* __restrict__ W) {
    const int n = (blockIdx.x & 1) * 256 + threadIdx.x;
    const int k0 = (blockIdx.x >> 1) * 8;
    unsigned short hi[8], lo[8];
#pragma unroll
    for (int u = 0; u < 8; ++u) {
        float r;
        hi[u] = bf_hi(W[(size_t)(k0 + u) * 512 + n], r);
        lo[u] = __bfloat16_as_ushort(__float2bfloat16(r));
    }
    uint4 vh, vl;
    vh.x = (uint32_t)hi[0] | ((uint32_t)hi[1] << 16);
    vh.y = (uint32_t)hi[2] | ((uint32_t)hi[3] << 16);
    vh.z = (uint32_t)hi[4] | ((uint32_t)hi[5] << 16);
    vh.w = (uint32_t)hi[6] | ((uint32_t)hi[7] << 16);
    vl.x = (uint32_t)lo[0] | ((uint32_t)lo[1] << 16);
    vl.y = (uint32_t)lo[2] | ((uint32_t)lo[3] << 16);
    vl.z = (uint32_t)lo[4] | ((uint32_t)lo[5] << 16);
    vl.w = (uint32_t)lo[6] | ((uint32_t)lo[7] << 16);
    *reinterpret_cast<uint4*>(&g_Wh[(size_t)n * WPITCH + k0]) = vh;
    *reinterpret_cast<uint4*>(&g_Wl[(size_t)n * WPITCH + k0]) = vl;
}

// ---------------------------------------------------------------------------
// K1: h = x @ W + b via mma.sync bf16 split, W tiles DOUBLE-BUFFERED:
// cp.async for chunk kc+1 issued before compute(kc) -> load hidden by MMAs.
// ---------------------------------------------------------------------------
#define G_AH 0
#define G_AL 18432
#define G_B0 36864          // stage 0: BH | BL (18432 each)
#define G_BSTAGE 36864
#define G_TOTAL 110592      // 36864*3 -> still 2 CTAs/SM

__global__ __launch_bounds__(256, 2) void gemm_mma_kernel(
    const float* __restrict__ x, const float* __restrict__ bias) {
    extern __shared__ char smem[];
    const uint32_t sb = smem_u32(smem);
    const int tid = threadIdx.x;
    const int wid = tid >> 5, lane = tid & 31;
    const int g = lane >> 2, tg = lane & 3;
    const int mw = wid & 3, nw = wid >> 2;
    const int gm0 = blockIdx.y * 128;
    const int gn0 = blockIdx.x * 128;

    float acc[2][8][4];
#pragma unroll
    for (int mt = 0; mt < 2; ++mt)
#pragma unroll
        for (int nt = 0; nt < 8; ++nt)
#pragma unroll
            for (int e = 0; e < 4; ++e) acc[mt][nt][e] = 0.f;

    const int xm = tid >> 1, xh4 = (tid & 1) * 32;
    const int brow = tid >> 3, bseg = (tid & 7) * 8;

    auto issueB = [&](int kc, int stage) {
        const uint32_t stb = sb + G_B0 + stage * G_BSTAGE;
#pragma unroll
        for (int it = 0; it < 4; ++it) {
            const int row = brow + it * 32;
            cp_async16(stb + row * 144 + bseg * 2,
                       &g_Wh[(size_t)(gn0 + row) * WPITCH + kc * 64 + bseg]);
            cp_async16(stb + 18432 + row * 144 + bseg * 2,
                       &g_Wl[(size_t)(gn0 + row) * WPITCH + kc * 64 + bseg]);
        }
        asm volatile("cp.async.commit_group;" ::: "memory");
    };
    auto packA = [&](int kc) {
        const float4* xs = reinterpret_cast<const float4*>(
            x + (size_t)(gm0 + xm) * 512 + kc * 64 + xh4);
        unsigned short sh[32], sl[32];
#pragma unroll
        for (int q = 0; q < 8; ++q) {
            float4 v = xs[q];
            float r0, r1, r2, r3;
            sh[q * 4 + 0] = bf_hi(v.x, r0); sh[q * 4 + 1] = bf_hi(v.y, r1);
            sh[q * 4 + 2] = bf_hi(v.z, r2); sh[q * 4 + 3] = bf_hi(v.w, r3);
            sl[q * 4 + 0] = __bfloat16_as_ushort(__float2bfloat16(r0));
            sl[q * 4 + 1] = __bfloat16_as_ushort(__float2bfloat16(r1));
            sl[q * 4 + 2] = __bfloat16_as_ushort(__float2bfloat16(r2));
            sl[q * 4 + 3] = __bfloat16_as_ushort(__float2bfloat16(r3));
        }
        char* ah = smem + G_AH + xm * 144 + xh4 * 2;
        char* al = smem + G_AL + xm * 144 + xh4 * 2;
#pragma unroll
        for (int q = 0; q < 4; ++q) {
            uint4 v;
            v.x = (uint32_t)sh[q * 8 + 0] | ((uint32_t)sh[q * 8 + 1] << 16);
            v.y = (uint32_t)sh[q * 8 + 2] | ((uint32_t)sh[q * 8 + 3] << 16);
            v.z = (uint32_t)sh[q * 8 + 4] | ((uint32_t)sh[q * 8 + 5] << 16);
            v.w = (uint32_t)sh[q * 8 + 6] | ((uint32_t)sh[q * 8 + 7] << 16);
            *reinterpret_cast<uint4*>(ah + q * 16) = v;
            uint4 w;
            w.x = (uint32_t)sl[q * 8 + 0] | ((uint32_t)sl[q * 8 + 1] << 16);
            w.y = (uint32_t)sl[q * 8 + 2] | ((uint32_t)sl[q * 8 + 3] << 16);
            w.z = (uint32_t)sl[q * 8 + 4] | ((uint32_t)sl[q * 8 + 5] << 16);
            w.w = (uint32_t)sl[q * 8 + 6] | ((uint32_t)sl[q * 8 + 7] << 16);
            *reinterpret_cast<uint4*>(al + q * 16) = w;
        }
    };

    issueB(0, 0);
    packA(0);
    asm volatile("cp.async.wait_group 0;" ::: "memory");
    __syncthreads();

    for (int kc = 0; kc < 8; ++kc) {
        if (kc < 7) issueB(kc + 1, (kc + 1) & 1);
        const uint32_t stb = sb + G_B0 + (kc & 1) * G_BSTAGE;
        const uint32_t bb = stb + (lane & 7) * 144 + ((lane >> 3) & 1) * 16 +
                            (nw * 64) * 144;
#pragma unroll
        for (int s = 0; s < 4; ++s) {
            uint32_t ah[2][4], al[2][4];
#pragma unroll
            for (int mt = 0; mt < 2; ++mt) {
                const int mr = mw * 32 + mt * 16;
                const uint32_t ra = (mr + g) * 144 + (s * 16 + tg * 2) * 2;
                const uint32_t rb = (mr + g + 8) * 144 + (s * 16 + tg * 2) * 2;
                ah[mt][0] = *reinterpret_cast<const uint32_t*>(smem + G_AH + ra);
                ah[mt][1] = *reinterpret_cast<const uint32_t*>(smem + G_AH + rb);
                ah[mt][2] = *reinterpret_cast<const uint32_t*>(smem + G_AH + ra + 16);
                ah[mt][3] = *reinterpret_cast<const uint32_t*>(smem + G_AH + rb + 16);
                al[mt][0] = *reinterpret_cast<const uint32_t*>(smem + G_AL + ra);
                al[mt][1] = *reinterpret_cast<const uint32_t*>(smem + G_AL + rb);
                al[mt][2] = *reinterpret_cast<const uint32_t*>(smem + G_AL + ra + 16);
                al[mt][3] = *reinterpret_cast<const uint32_t*>(smem + G_AL + rb + 16);
            }
#pragma unroll
            for (int nt = 0; nt < 8; ++nt) {
                uint32_t bh0, bh1, bl0, bl1;
                const uint32_t bo = bb + nt * 8 * 144 + s * 32;
                ldsm_x2(bh0, bh1, bo);
                ldsm_x2(bl0, bl1, bo + 18432);
#pragma unroll
                for (int mt = 0; mt < 2; ++mt) {
                    mma16816(acc[mt][nt], ah[mt], bh0, bh1);
                    mma16816(acc[mt][nt], al[mt], bh0, bh1);
                    mma16816(acc[mt][nt], ah[mt], bl0, bl1);
                }
            }
        }
        if (kc < 7) {
            __syncthreads();      // everyone done reading A(kc)
            packA(kc + 1);
            asm volatile("cp.async.wait_group 0;" ::: "memory");
            __syncthreads();
        }
    }
#pragma unroll
    for (int nt = 0; nt < 8; ++nt) {
        const int col = gn0 + nw * 64 + nt * 8 + tg * 2;
        const float b0 = __ldg(&bias[col]), b1 = __ldg(&bias[col + 1]);
#pragma unroll
        for (int mt = 0; mt < 2; ++mt) {
            const int row = gm0 + mw * 32 + mt * 16 + g;
            float2 v0 = {acc[mt][nt][0] + b0, acc[mt][nt][1] + b1};
            float2 v1 = {acc[mt][nt][2] + b0, acc[mt][nt][3] + b1};
            *reinterpret_cast<float2*>(&g_h[(size_t)row * 512 + col]) = v0;
            *reinterpret_cast<float2*>(&g_h[(size_t)(row + 8) * 512 + col]) = v1;
        }
    }
}

// ---------------------------------------------------------------------------
// K2: decayed scan — batched loads for MLP
// ---------------------------------------------------------------------------
__global__ void scan_local_kernel() {
    const int tid = blockIdx.x * blockDim.x + threadIdx.x;
    const int m = tid >> 12, c = tid & 4095;
    const int b = c >> 9, hd = c & 511;
    const float* hp = g_h + (size_t)(b * Tn + m * CHUNK) * En + hd;
    float s = 0.f;
    for (int t0 = 0; t0 < CHUNK; t0 += 8) {
        float buf[8];
#pragma unroll
        for (int u = 0; u < 8; ++u) buf[u] = hp[(size_t)(t0 + u) * En];
#pragma unroll
        for (int u = 0; u < 8; ++u) s = (s + buf[u]) * INV_DECAY;
    }
    g_local[m * NCH + c] = s;
}
__global__ void scan_emit_kernel() {
    const int tid = blockIdx.x * blockDim.x + threadIdx.x;
    const int m = tid >> 12, c = tid & 4095;
    const int b = c >> 9, hd = c & 511;
    float r = 1.f;
#pragma unroll
    for (int q = 0; q < CHUNK; ++q) r *= INV_DECAY;
    float s = 0.f;
    for (int mm = 0; mm < m; ++mm) s = s * r + g_local[mm * NCH + c];
    const float* hp = g_h + (size_t)(b * Tn + m * CHUNK) * En + hd;
    float* Sp = g_S + (size_t)(b * Tn + m * CHUNK) * En + hd;
    for (int t0 = 0; t0 < CHUNK; t0 += 8) {
        float buf[8], sv[8];
#pragma unroll
        for (int u = 0; u < 8; ++u) buf[u] = hp[(size_t)(t0 + u) * En];
#pragma unroll
        for (int u = 0; u < 8; ++u) {
            sv[u] = s;
            s = (s + buf[u]) * INV_DECAY;
        }
#pragma unroll
        for (int u = 0; u < 8; ++u) Sp[(size_t)(t0 + u) * En] = sv[u];
    }
}

// ---------------------------------------------------------------------------
// K3: bilinear via mma.sync bf16 split — 256 tokens/block, 8 warps x 2 m-tiles.
// Accumulator split d0/d1 per m-tile -> 4 independent MMA chains per warp.
// ---------------------------------------------------------------------------
#define SM_A 0            // 256*144  = 36864
#define SM_B 36864        // 1024*144 = 147456
#define SM_Y 184320       // 256*33*4 = 33792
#define SM_TOTAL 218112

__global__ __launch_bounds__(256, 1) void bilinear_mma_kernel() {
    extern __shared__ char smem[];
    const uint32_t sb = smem_u32(smem);
    const int tid = threadIdx.x;
    const int wid = tid >> 5, lane = tid & 31;
    const int head = blockIdx.y;
    const int tok0 = blockIdx.x * 256;
    float* ys = reinterpret_cast<float*>(smem + SM_Y);

    // C prefetch FIRST (hidden behind A pack)
    {
        const uint4* gsrc = g_Cpack + (size_t)head * 9216;
#pragma unroll
        for (int t = 0; t < 36; ++t) {
            const int gidx = tid + t * 256;
            cp_async16(sb + SM_B + gidx * 16, gsrc + gidx);
        }
        asm volatile("cp.async.commit_group;" ::: "memory");
    }

    // A pack: each thread packs one of 256 rows
    {
        const int r = tid;
        const float* Sp = &g_S[(size_t)(tok0 + r) * 512 + head * 32];
        unsigned short sh[32], sl[32];
#pragma unroll
        for (int q = 0; q < 8; ++q) {
            float4 v = *reinterpret_cast<const float4*>(Sp + q * 4);
            float r0, r1, r2, r3;
            sh[q * 4 + 0] = bf_hi(v.x, r0); sh[q * 4 + 1] = bf_hi(v.y, r1);
            sh[q * 4 + 2] = bf_hi(v.z, r2); sh[q * 4 + 3] = bf_hi(v.w, r3);
            sl[q * 4 + 0] = __bfloat16_as_ushort(__float2bfloat16(r0));
            sl[q * 4 + 1] = __bfloat16_as_ushort(__float2bfloat16(r1));
            sl[q * 4 + 2] = __bfloat16_as_ushort(__float2bfloat16(r2));
            sl[q * 4 + 3] = __bfloat16_as_ushort(__float2bfloat16(r3));
        }
        uint4* arow = reinterpret_cast<uint4*>(smem + SM_A + r * 144);
#pragma unroll
        for (int q = 0; q < 4; ++q) {
            uint4 v;
            v.x = (uint32_t)sh[q * 8 + 0] | ((uint32_t)sh[q * 8 + 1] << 16);
            v.y = (uint32_t)sh[q * 8 + 2] | ((uint32_t)sh[q * 8 + 3] << 16);
            v.z = (uint32_t)sh[q * 8 + 4] | ((uint32_t)sh[q * 8 + 5] << 16);
            v.w = (uint32_t)sh[q * 8 + 6] | ((uint32_t)sh[q * 8 + 7] << 16);
            arow[q] = v;
            uint4 w;
            w.x = (uint32_t)sl[q * 8 + 0] | ((uint32_t)sl[q * 8 + 1] << 16);
            w.y = (uint32_t)sl[q * 8 + 2] | ((uint32_t)sl[q * 8 + 3] << 16);
            w.z = (uint32_t)sl[q * 8 + 4] | ((uint32_t)sl[q * 8 + 5] << 16);
            w.w = (uint32_t)sl[q * 8 + 6] | ((uint32_t)sl[q * 8 + 7] << 16);
            arow[4 + q] = w;
        }
    }
    asm volatile("cp.async.wait_group 0;" ::: "memory");
    __syncthreads();

    {
        const int g = lane >> 2, tg = lane & 3;
        uint32_t afr[2][4][4];
        float hreg[2][4][4];
#pragma unroll
        for (int mt = 0; mt < 2; ++mt) {
            const int mr = (wid * 2 + mt) * 16;
#pragma unroll
            for (int s = 0; s < 4; ++s) {
                const char* base = smem + SM_A;
                const uint32_t ra = (mr + g) * 144 + (s * 16 + tg * 2) * 2;
                const uint32_t rb = (mr + g + 8) * 144 + (s * 16 + tg * 2) * 2;
                afr[mt][s][0] = *reinterpret_cast<const uint32_t*>(base + ra);
                afr[mt][s][1] = *reinterpret_cast<const uint32_t*>(base + rb);
                afr[mt][s][2] = *reinterpret_cast<const uint32_t*>(base + ra + 16);
                afr[mt][s][3] = *reinterpret_cast<const uint32_t*>(base + rb + 16);
            }
#pragma unroll
            for (int it = 0; it < 4; ++it) {
                const int i0 = it * 8 + tg * 2;
                float2 va = *reinterpret_cast<const float2*>(
                    &g_h[(size_t)(tok0 + mr + g) * 512 + head * 32 + i0]);
                float2 vb = *reinterpret_cast<const float2*>(
                    &g_h[(size_t)(tok0 + mr + g + 8) * 512 + head * 32 + i0]);
                hreg[mt][it][0] = va.x; hreg[mt][it][1] = va.y;
                hreg[mt][it][2] = vb.x; hreg[mt][it][3] = vb.y;
            }
        }
        const uint32_t bb4 = sb + SM_B + (lane & 7) * 144 + ((lane >> 3) & 3) * 16;

        for (int k = 0; k < 32; ++k) {
            float yA0 = 0.f, yB0 = 0.f, yA1 = 0.f, yB1 = 0.f;
#pragma unroll
            for (int it = 0; it < 4; ++it) {
                const uint32_t boff = bb4 + (uint32_t)(k * 32 + it * 8) * 144;
                uint32_t bh[4], bl[4];
                ldsm_x4(bh, boff);        // Ch
                ldsm_x4(bl, boff + 64);   // Cl
                // 4 independent chains: d0[mt] (2 deep), d1[mt] (4 deep)
                float d0a[4] = {0.f, 0.f, 0.f, 0.f}, d0b[4] = {0.f, 0.f, 0.f, 0.f};
                float d1a[4] = {0.f, 0.f, 0.f, 0.f}, d1b[4] = {0.f, 0.f, 0.f, 0.f};
                mma16816(d0a, afr[0][0], bh[0], bh[1]);   // mt0 Sh.Ch lo
                mma16816(d0b, afr[1][0], bh[0], bh[1]);   // mt1 Sh.Ch lo
                mma16816(d1a, afr[0][2], bh[0], bh[1]);   // mt0 Sl.Ch lo
                mma16816(d1b, afr[1][2], bh[0], bh[1]);   // mt1 Sl.Ch lo
                mma16816(d0a, afr[0][1], bh[2], bh[3]);   // mt0 Sh.Ch hi
                mma16816(d0b, afr[1][1], bh[2], bh[3]);   // mt1 Sh.Ch hi
                mma16816(d1a, afr[0][3], bh[2], bh[3]);   // mt0 Sl.Ch hi
                mma16816(d1b, afr[1][3], bh[2], bh[3]);   // mt1 Sl.Ch hi
                mma16816(d1a, afr[0][0], bl[0], bl[1]);   // mt0 Sh.Cl lo
                mma16816(d1b, afr[1][0], bl[0], bl[1]);   // mt1 Sh.Cl lo
                mma16816(d1a, afr[0][1], bl[2], bl[3]);   // mt0 Sh.Cl hi
                mma16816(d1b, afr[1][1], bl[2], bl[3]);   // mt1 Sh.Cl hi
                yA0 = fmaf(d0a[0] + d1a[0], hreg[0][it][0],
                      fmaf(d0a[1] + d1a[1], hreg[0][it][1], yA0));
                yB0 = fmaf(d0a[2] + d1a[2], hreg[0][it][2],
                      fmaf(d0a[3] + d1a[3], hreg[0][it][3], yB0));
                yA1 = fmaf(d0b[0] + d1b[0], hreg[1][it][0],
                      fmaf(d0b[1] + d1b[1], hreg[1][it][1], yA1));
                yB1 = fmaf(d0b[2] + d1b[2], hreg[1][it][2],
                      fmaf(d0b[3] + d1b[3], hreg[1][it][3], yB1));
            }
#pragma unroll
            for (int o = 1; o <= 2; o <<= 1) {
                yA0 += __shfl_xor_sync(0xffffffffu, yA0, o);
                yB0 += __shfl_xor_sync(0xffffffffu, yB0, o);
                yA1 += __shfl_xor_sync(0xffffffffu, yA1, o);
                yB1 += __shfl_xor_sync(0xffffffffu, yB1, o);
            }
            if (tg == (k & 3)) {
                const int mrA = (wid * 2) * 16, mrB = (wid * 2 + 1) * 16;
                ys[(mrA + g) * 33 + k] = yA0;
                ys[(mrA + g + 8) * 33 + k] = yB0;
                ys[(mrB + g) * 33 + k] = yA1;
                ys[(mrB + g + 8) * 33 + k] = yB1;
            }
        }
    }
    __syncthreads();

    // residual (re-read g_h from L2) + coalesced store
#pragma unroll
    for (int p = 0; p < 8; ++p) {
        const int idx = tid + p * 256;
        const int r = idx >> 3, c = (idx & 7) * 4;
        const float4 hv = *reinterpret_cast<const float4*>(
            &g_h[(size_t)(tok0 + r) * 512 + head * 32 + c]);
        float4 v;
        v.x = ys[r * 33 + c + 0] + hv.x;
        v.y = ys[r * 33 + c + 1] + hv.y;
        v.z = ys[r * 33 + c + 2] + hv.z;
        v.w = ys[r * 33 + c + 3] + hv.w;
        *reinterpret_cast<float4*>(
            &g_y[(size_t)(tok0 + r) * 512 + head * 32 + c]) = v;
    }
}

// ---------------------------------------------------------------------------
// K4: LayerNorm
// ---------------------------------------------------------------------------
__global__ __launch_bounds__(256) void ln_kernel(const float* __restrict__ gamma,
                                                 const float* __restrict__ beta,
                                                 float* __restrict__ out) {
    const int w = threadIdx.x >> 5, lane = threadIdx.x & 31;
    const int token = blockIdx.x * 8 + w;
    const float* yp = g_y + (size_t)token * En;
    float vals[16], sum = 0.f, sq = 0.f;
#pragma unroll
    for (int c2 = 0; c2 < 16; ++c2) {
        const float v = yp[c2 * 32 + lane];
        vals[c2] = v; sum += v; sq = fmaf(v, v, sq);
    }
#pragma unroll
    for (int o = 16; o; o >>= 1) {
        sum += __shfl_xor_sync(0xffffffffu, sum, o);
        sq += __shfl_xor_sync(0xffffffffu, sq, o);
    }
    const float mu = sum * (1.f / 512.f);
    const float var = sq * (1.f / 512.f) - mu * mu;
    const float inv = rsqrtf(var + LN_EPS);
    float* op = out + (size_t)token * En;
#pragma unroll
    for (int c2 = 0; c2 < 16; ++c2) {
        const int e = c2 * 32 + lane;
        op[e] = (vals[c2] - mu) * inv * gamma[e] + beta[e];
    }
}

// ---------------------------------------------------------------------------
extern "C" void kernel_launch(void* const* d_in, const int* in_sizes, int n_in,
                              void* d_out, int out_size) {
    const float* x = (const float*)d_in[0];
    const float* W = (const float*)d_in[1];
    const float* bias = (const float*)d_in[2];
    const float* cmap = (const float*)d_in[3];
    const float* gamma = (const float*)d_in[4];
    const float* beta = (const float*)d_in[5];
    float* out = (float*)d_out;

    static int smem_set = 0;
    if (!smem_set) {
        cudaFuncSetAttribute(bilinear_mma_kernel,
                             cudaFuncAttributeMaxDynamicSharedMemorySize, SM_TOTAL);
        cudaFuncSetAttribute(gemm_mma_kernel,
                             cudaFuncAttributeMaxDynamicSharedMemorySize, G_TOTAL);
        smem_set = 1;
    }

    cpack_kernel<<<64, 256>>>(cmap);
    wpack_kernel<<<128, 256>>>(W);
    gemm_mma_kernel<<<dim3(4, 128), 256, G_TOTAL>>>(x, bias);
    scan_local_kernel<<<NCHUNK * NCH / 256, 256>>>();
    scan_emit_kernel<<<NCHUNK * NCH / 256, 256>>>();
    bilinear_mma_kernel<<<dim3(64, Hn), 256, SM_TOTAL>>>();
    ln_kernel<<<BT / 8, 256>>>(gamma, beta, out);
}

// round 10
// speedup vs baseline: 1.1834x; 1.1834x over previous
#include <cuda_runtime.h>
#include <cuda_bf16.h>
#include <cuda_fp16.h>
#include <cstdint>

// ConceptLayer: h = xW+b ; S = decayed scan ; y = bilinear(h,S;C)+h ; LayerNorm
// B=8 T=2048 E=512 H=16 D=32.  sm_100-safe: mma.sync (HMMA), cp.async, ldmatrix.
#define Bn 8
#define Tn 2048
#define En 512
#define Hn 16
#define BT (Bn * Tn)
#define LN_EPS 1e-3f
#define INV_DECAY (1.0f / 1.2f)
#define CHUNK 128
#define NCHUNK (Tn / CHUNK)
#define NCH (Bn * En)
#define WPITCH 520

__device__ float g_h[BT * En];
__device__ float g_S[BT * En];
__device__ float g_y[BT * En];
__device__ float g_local[NCHUNK * NCH];
// C packed split-fp16: [head][n=k*32+i][72 fp16] = [Ch | Cl | pad]
__device__ uint4 g_Cpack[Hn * 1024 * 9];
// W packed transposed split-bf16: [n][k] pitch 520
__device__ __nv_bfloat16 g_Wh[512 * WPITCH];
__device__ __nv_bfloat16 g_Wl[512 * WPITCH];

__device__ __forceinline__ unsigned short bf_hi(float v, float& rem) {
    __nv_bfloat16 h = __float2bfloat16(v);
    rem = v - __bfloat162float(h);
    return __bfloat16_as_ushort(h);
}
__device__ __forceinline__ uint32_t smem_u32(const void* p) {
    uint32_t a;
    asm("{ .reg .u64 t; cvta.to.shared.u64 t, %1; cvt.u32.u64 %0, t; }" : "=r"(a) : "l"(p));
    return a;
}
// bf16 MMA (GEMM)
__device__ __forceinline__ void mma16816(float* d, const uint32_t* a, uint32_t b0, uint32_t b1) {
    asm volatile(
        "mma.sync.aligned.m16n8k16.row.col.f32.bf16.bf16.f32 "
        "{%0,%1,%2,%3}, {%4,%5,%6,%7}, {%8,%9}, {%0,%1,%2,%3};"
        : "+f"(d[0]), "+f"(d[1]), "+f"(d[2]), "+f"(d[3])
        : "r"(a[0]), "r"(a[1]), "r"(a[2]), "r"(a[3]), "r"(b0), "r"(b1));
}
// fp16 MMA (bilinear)
__device__ __forceinline__ void mma16816h(float* d, const uint32_t* a, uint32_t b0, uint32_t b1) {
    asm volatile(
        "mma.sync.aligned.m16n8k16.row.col.f32.f16.f16.f32 "
        "{%0,%1,%2,%3}, {%4,%5,%6,%7}, {%8,%9}, {%0,%1,%2,%3};"
        : "+f"(d[0]), "+f"(d[1]), "+f"(d[2]), "+f"(d[3])
        : "r"(a[0]), "r"(a[1]), "r"(a[2]), "r"(a[3]), "r"(b0), "r"(b1));
}
__device__ __forceinline__ void ldsm_x2(uint32_t& r0, uint32_t& r1, uint32_t addr) {
    asm volatile("ldmatrix.sync.aligned.m8n8.x2.shared.b16 {%0,%1}, [%2];"
                 : "=r"(r0), "=r"(r1) : "r"(addr));
}
__device__ __forceinline__ void ldsm_x4(uint32_t* r, uint32_t addr) {
    asm volatile("ldmatrix.sync.aligned.m8n8.x4.shared.b16 {%0,%1,%2,%3}, [%4];"
                 : "=r"(r[0]), "=r"(r[1]), "=r"(r[2]), "=r"(r[3]) : "r"(addr));
}
__device__ __forceinline__ void cp_async16(uint32_t dst, const void* src) {
    asm volatile("cp.async.cg.shared.global [%0], [%1], 16;" :: "r"(dst), "l"(src) : "memory");
}

// ---------------------------------------------------------------------------
// K0a: pack C -> split fp16 [head][n][72] = [Ch(32) | Cl(32) | pad(8)]
// ---------------------------------------------------------------------------
__global__ void cpack_kernel(const float* __restrict__ C) {
    const int idx = blockIdx.x * 256 + threadIdx.x;
    const float* src = C + (size_t)idx * 32;
    unsigned short hi[32], lo[32];
#pragma unroll
    for (int j = 0; j < 32; ++j) {
        const float v = src[j];
        const __half h = __float2half(v);
        hi[j] = __half_as_ushort(h);
        lo[j] = __half_as_ushort(__float2half(v - __half2float(h)));
    }
    uint4* dst = g_Cpack + (size_t)idx * 9;
#pragma unroll
    for (int q = 0; q < 4; ++q) {
        uint4 v;
        v.x = (uint32_t)hi[q * 8 + 0] | ((uint32_t)hi[q * 8 + 1] << 16);
        v.y = (uint32_t)hi[q * 8 + 2] | ((uint32_t)hi[q * 8 + 3] << 16);
        v.z = (uint32_t)hi[q * 8 + 4] | ((uint32_t)hi[q * 8 + 5] << 16);
        v.w = (uint32_t)hi[q * 8 + 6] | ((uint32_t)hi[q * 8 + 7] << 16);
        dst[q] = v;
        uint4 w;
        w.x = (uint32_t)lo[q * 8 + 0] | ((uint32_t)lo[q * 8 + 1] << 16);
        w.y = (uint32_t)lo[q * 8 + 2] | ((uint32_t)lo[q * 8 + 3] << 16);
        w.z = (uint32_t)lo[q * 8 + 4] | ((uint32_t)lo[q * 8 + 5] << 16);
        w.w = (uint32_t)lo[q * 8 + 6] | ((uint32_t)lo[q * 8 + 7] << 16);
        dst[4 + q] = w;
    }
}

// ---------------------------------------------------------------------------
// K0b: pack W [k][n] f32 -> g_Wh/g_Wl [n][k] bf16, pitch WPITCH
// ---------------------------------------------------------------------------
__global__ void wpack_kernel(const float* __restrict__ W) {
    const int n = (blockIdx.x & 1) * 256 + threadIdx.x;
    const int k0 = (blockIdx.x >> 1) * 8;
    unsigned short hi[8], lo[8];
#pragma unroll
    for (int u = 0; u < 8; ++u) {
        float r;
        hi[u] = bf_hi(W[(size_t)(k0 + u) * 512 + n], r);
        lo[u] = __bfloat16_as_ushort(__float2bfloat16(r));
    }
    uint4 vh, vl;
    vh.x = (uint32_t)hi[0] | ((uint32_t)hi[1] << 16);
    vh.y = (uint32_t)hi[2] | ((uint32_t)hi[3] << 16);
    vh.z = (uint32_t)hi[4] | ((uint32_t)hi[5] << 16);
    vh.w = (uint32_t)hi[6] | ((uint32_t)hi[7] << 16);
    vl.x = (uint32_t)lo[0] | ((uint32_t)lo[1] << 16);
    vl.y = (uint32_t)lo[2] | ((uint32_t)lo[3] << 16);
    vl.z = (uint32_t)lo[4] | ((uint32_t)lo[5] << 16);
    vl.w = (uint32_t)lo[6] | ((uint32_t)lo[7] << 16);
    *reinterpret_cast<uint4*>(&g_Wh[(size_t)n * WPITCH + k0]) = vh;
    *reinterpret_cast<uint4*>(&g_Wl[(size_t)n * WPITCH + k0]) = vl;
}

// ---------------------------------------------------------------------------
// K1: h = x @ W + b via mma.sync bf16 split (R8 known-good, single-buffered)
// ---------------------------------------------------------------------------
#define G_AH 0
#define G_AL 18432
#define G_BH 36864
#define G_BL 55296
#define G_TOTAL 73728

__global__ __launch_bounds__(256, 2) void gemm_mma_kernel(
    const float* __restrict__ x, const float* __restrict__ bias) {
    extern __shared__ char smem[];
    const uint32_t sb = smem_u32(smem);
    const int tid = threadIdx.x;
    const int wid = tid >> 5, lane = tid & 31;
    const int g = lane >> 2, tg = lane & 3;
    const int mw = wid & 3, nw = wid >> 2;
    const int gm0 = blockIdx.y * 128;
    const int gn0 = blockIdx.x * 128;

    float acc[2][8][4];
#pragma unroll
    for (int mt = 0; mt < 2; ++mt)
#pragma unroll
        for (int nt = 0; nt < 8; ++nt)
#pragma unroll
            for (int e = 0; e < 4; ++e) acc[mt][nt][e] = 0.f;

    const int xm = tid >> 1, xh4 = (tid & 1) * 32;
    const uint32_t a_h_dst = sb + G_AH + xm * 144 + xh4 * 2;
    const uint32_t a_l_dst = sb + G_AL + xm * 144 + xh4 * 2;
    const int brow = tid >> 3, bseg = (tid & 7) * 8;

    for (int kc = 0; kc < 8; ++kc) {
#pragma unroll
        for (int it = 0; it < 4; ++it) {
            const int row = brow + it * 32;
            cp_async16(sb + G_BH + row * 144 + bseg * 2,
                       &g_Wh[(size_t)(gn0 + row) * WPITCH + kc * 64 + bseg]);
            cp_async16(sb + G_BL + row * 144 + bseg * 2,
                       &g_Wl[(size_t)(gn0 + row) * WPITCH + kc * 64 + bseg]);
        }
        asm volatile("cp.async.commit_group;" ::: "memory");
        {
            const float4* xs = reinterpret_cast<const float4*>(
                x + (size_t)(gm0 + xm) * 512 + kc * 64 + xh4);
            unsigned short sh[32], sl[32];
#pragma unroll
            for (int q = 0; q < 8; ++q) {
                float4 v = xs[q];
                float r0, r1, r2, r3;
                sh[q * 4 + 0] = bf_hi(v.x, r0); sh[q * 4 + 1] = bf_hi(v.y, r1);
                sh[q * 4 + 2] = bf_hi(v.z, r2); sh[q * 4 + 3] = bf_hi(v.w, r3);
                sl[q * 4 + 0] = __bfloat16_as_ushort(__float2bfloat16(r0));
                sl[q * 4 + 1] = __bfloat16_as_ushort(__float2bfloat16(r1));
                sl[q * 4 + 2] = __bfloat16_as_ushort(__float2bfloat16(r2));
                sl[q * 4 + 3] = __bfloat16_as_ushort(__float2bfloat16(r3));
            }
#pragma unroll
            for (int q = 0; q < 4; ++q) {
                uint4 v;
                v.x = (uint32_t)sh[q * 8 + 0] | ((uint32_t)sh[q * 8 + 1] << 16);
                v.y = (uint32_t)sh[q * 8 + 2] | ((uint32_t)sh[q * 8 + 3] << 16);
                v.z = (uint32_t)sh[q * 8 + 4] | ((uint32_t)sh[q * 8 + 5] << 16);
                v.w = (uint32_t)sh[q * 8 + 6] | ((uint32_t)sh[q * 8 + 7] << 16);
                *reinterpret_cast<uint4*>(smem + (a_h_dst - sb) + q * 16) = v;
                uint4 w;
                w.x = (uint32_t)sl[q * 8 + 0] | ((uint32_t)sl[q * 8 + 1] << 16);
                w.y = (uint32_t)sl[q * 8 + 2] | ((uint32_t)sl[q * 8 + 3] << 16);
                w.z = (uint32_t)sl[q * 8 + 4] | ((uint32_t)sl[q * 8 + 5] << 16);
                w.w = (uint32_t)sl[q * 8 + 6] | ((uint32_t)sl[q * 8 + 7] << 16);
                *reinterpret_cast<uint4*>(smem + (a_l_dst - sb) + q * 16) = w;
            }
        }
        asm volatile("cp.async.wait_group 0;" ::: "memory");
        __syncthreads();

        const uint32_t bb = sb + (lane & 7) * 144 + ((lane >> 3) & 1) * 16 +
                            (nw * 64) * 144;
#pragma unroll
        for (int s = 0; s < 4; ++s) {
            uint32_t ah[2][4], al[2][4];
#pragma unroll
            for (int mt = 0; mt < 2; ++mt) {
                const int mr = mw * 32 + mt * 16;
                const uint32_t ra = (mr + g) * 144 + (s * 16 + tg * 2) * 2;
                const uint32_t rb = (mr + g + 8) * 144 + (s * 16 + tg * 2) * 2;
                ah[mt][0] = *reinterpret_cast<const uint32_t*>(smem + G_AH + ra);
                ah[mt][1] = *reinterpret_cast<const uint32_t*>(smem + G_AH + rb);
                ah[mt][2] = *reinterpret_cast<const uint32_t*>(smem + G_AH + ra + 16);
                ah[mt][3] = *reinterpret_cast<const uint32_t*>(smem + G_AH + rb + 16);
                al[mt][0] = *reinterpret_cast<const uint32_t*>(smem + G_AL + ra);
                al[mt][1] = *reinterpret_cast<const uint32_t*>(smem + G_AL + rb);
                al[mt][2] = *reinterpret_cast<const uint32_t*>(smem + G_AL + ra + 16);
                al[mt][3] = *reinterpret_cast<const uint32_t*>(smem + G_AL + rb + 16);
            }
#pragma unroll
            for (int nt = 0; nt < 8; ++nt) {
                uint32_t bh0, bh1, bl0, bl1;
                const uint32_t bo = bb + nt * 8 * 144 + s * 32;
                ldsm_x2(bh0, bh1, bo + G_BH);
                ldsm_x2(bl0, bl1, bo + G_BL);
#pragma unroll
                for (int mt = 0; mt < 2; ++mt) {
                    mma16816(acc[mt][nt], ah[mt], bh0, bh1);
                    mma16816(acc[mt][nt], al[mt], bh0, bh1);
                    mma16816(acc[mt][nt], ah[mt], bl0, bl1);
                }
            }
        }
        __syncthreads();
    }
#pragma unroll
    for (int nt = 0; nt < 8; ++nt) {
        const int col = gn0 + nw * 64 + nt * 8 + tg * 2;
        const float b0 = __ldg(&bias[col]), b1 = __ldg(&bias[col + 1]);
#pragma unroll
        for (int mt = 0; mt < 2; ++mt) {
            const int row = gm0 + mw * 32 + mt * 16 + g;
            float2 v0 = {acc[mt][nt][0] + b0, acc[mt][nt][1] + b1};
            float2 v1 = {acc[mt][nt][2] + b0, acc[mt][nt][3] + b1};
            *reinterpret_cast<float2*>(&g_h[(size_t)row * 512 + col]) = v0;
            *reinterpret_cast<float2*>(&g_h[(size_t)(row + 8) * 512 + col]) = v1;
        }
    }
}

// ---------------------------------------------------------------------------
// K2: decayed scan — batched loads for MLP
// ---------------------------------------------------------------------------
__global__ void scan_local_kernel() {
    const int tid = blockIdx.x * blockDim.x + threadIdx.x;
    const int m = tid >> 12, c = tid & 4095;
    const int b = c >> 9, hd = c & 511;
    const float* hp = g_h + (size_t)(b * Tn + m * CHUNK) * En + hd;
    float s = 0.f;
    for (int t0 = 0; t0 < CHUNK; t0 += 8) {
        float buf[8];
#pragma unroll
        for (int u = 0; u < 8; ++u) buf[u] = hp[(size_t)(t0 + u) * En];
#pragma unroll
        for (int u = 0; u < 8; ++u) s = (s + buf[u]) * INV_DECAY;
    }
    g_local[m * NCH + c] = s;
}
__global__ void scan_emit_kernel() {
    const int tid = blockIdx.x * blockDim.x + threadIdx.x;
    const int m = tid >> 12, c = tid & 4095;
    const int b = c >> 9, hd = c & 511;
    float r = 1.f;
#pragma unroll
    for (int q = 0; q < CHUNK; ++q) r *= INV_DECAY;
    float s = 0.f;
    for (int mm = 0; mm < m; ++mm) s = s * r + g_local[mm * NCH + c];
    const float* hp = g_h + (size_t)(b * Tn + m * CHUNK) * En + hd;
    float* Sp = g_S + (size_t)(b * Tn + m * CHUNK) * En + hd;
    for (int t0 = 0; t0 < CHUNK; t0 += 8) {
        float buf[8], sv[8];
#pragma unroll
        for (int u = 0; u < 8; ++u) buf[u] = hp[(size_t)(t0 + u) * En];
#pragma unroll
        for (int u = 0; u < 8; ++u) {
            sv[u] = s;
            s = (s + buf[u]) * INV_DECAY;
        }
#pragma unroll
        for (int u = 0; u < 8; ++u) Sp[(size_t)(t0 + u) * En] = sv[u];
    }
}

// ---------------------------------------------------------------------------
// K3: bilinear via mma.sync fp16 (S single, C hi/lo -> 2 combos = 8 MMA/it).
// 256 tokens/block, 8 warps x 2 m-tiles; C frags via ldmatrix.x4.
// A: [256 rows][32 fp16] pitch 80B (conflict-free: 20-word stride).
// ---------------------------------------------------------------------------
#define SM_A 0            // 256*80   = 20480
#define SM_B 20480        // 1024*144 = 147456
#define SM_Y 167936       // 256*33*4 = 33792
#define SM_TOTAL 201728

__global__ __launch_bounds__(256, 1) void bilinear_mma_kernel() {
    extern __shared__ char smem[];
    const uint32_t sb = smem_u32(smem);
    const int tid = threadIdx.x;
    const int wid = tid >> 5, lane = tid & 31;
    const int head = blockIdx.y;
    const int tok0 = blockIdx.x * 256;
    float* ys = reinterpret_cast<float*>(smem + SM_Y);

    // C prefetch FIRST (hidden behind A pack)
    {
        const uint4* gsrc = g_Cpack + (size_t)head * 9216;
#pragma unroll
        for (int t = 0; t < 36; ++t) {
            const int gidx = tid + t * 256;
            cp_async16(sb + SM_B + gidx * 16, gsrc + gidx);
        }
        asm volatile("cp.async.commit_group;" ::: "memory");
    }

    // A pack: each thread packs one of 256 rows (S -> fp16 single)
    {
        const int r = tid;
        const float* Sp = &g_S[(size_t)(tok0 + r) * 512 + head * 32];
        unsigned short sh[32];
#pragma unroll
        for (int q = 0; q < 8; ++q) {
            float4 v = *reinterpret_cast<const float4*>(Sp + q * 4);
            sh[q * 4 + 0] = __half_as_ushort(__float2half(v.x));
            sh[q * 4 + 1] = __half_as_ushort(__float2half(v.y));
            sh[q * 4 + 2] = __half_as_ushort(__float2half(v.z));
            sh[q * 4 + 3] = __half_as_ushort(__float2half(v.w));
        }
        uint4* arow = reinterpret_cast<uint4*>(smem + SM_A + r * 80);
#pragma unroll
        for (int q = 0; q < 4; ++q) {
            uint4 v;
            v.x = (uint32_t)sh[q * 8 + 0] | ((uint32_t)sh[q * 8 + 1] << 16);
            v.y = (uint32_t)sh[q * 8 + 2] | ((uint32_t)sh[q * 8 + 3] << 16);
            v.z = (uint32_t)sh[q * 8 + 4] | ((uint32_t)sh[q * 8 + 5] << 16);
            v.w = (uint32_t)sh[q * 8 + 6] | ((uint32_t)sh[q * 8 + 7] << 16);
            arow[q] = v;
        }
    }
    asm volatile("cp.async.wait_group 0;" ::: "memory");
    __syncthreads();

    {
        const int g = lane >> 2, tg = lane & 3;
        // A fragments (2 k16-steps over j) + h registers, 2 m-tiles
        uint32_t afr[2][2][4];
        float hreg[2][4][4];
#pragma unroll
        for (int mt = 0; mt < 2; ++mt) {
            const int mr = (wid * 2 + mt) * 16;
#pragma unroll
            for (int s = 0; s < 2; ++s) {
                const char* base = smem + SM_A;
                const uint32_t ra = (mr + g) * 80 + s * 32 + tg * 4;
                const uint32_t rb = (mr + g + 8) * 80 + s * 32 + tg * 4;
                afr[mt][s][0] = *reinterpret_cast<const uint32_t*>(base + ra);
                afr[mt][s][1] = *reinterpret_cast<const uint32_t*>(base + rb);
                afr[mt][s][2] = *reinterpret_cast<const uint32_t*>(base + ra + 16);
                afr[mt][s][3] = *reinterpret_cast<const uint32_t*>(base + rb + 16);
            }
#pragma unroll
            for (int it = 0; it < 4; ++it) {
                const int i0 = it * 8 + tg * 2;
                float2 va = *reinterpret_cast<const float2*>(
                    &g_h[(size_t)(tok0 + mr + g) * 512 + head * 32 + i0]);
                float2 vb = *reinterpret_cast<const float2*>(
                    &g_h[(size_t)(tok0 + mr + g + 8) * 512 + head * 32 + i0]);
                hreg[mt][it][0] = va.x; hreg[mt][it][1] = va.y;
                hreg[mt][it][2] = vb.x; hreg[mt][it][3] = vb.y;
            }
        }
        const uint32_t bb4 = sb + SM_B + (lane & 7) * 144 + ((lane >> 3) & 3) * 16;

        for (int k = 0; k < 32; ++k) {
            float yA0 = 0.f, yB0 = 0.f, yA1 = 0.f, yB1 = 0.f;
#pragma unroll
            for (int it = 0; it < 4; ++it) {
                const uint32_t boff = bb4 + (uint32_t)(k * 32 + it * 8) * 144;
                uint32_t bh[4], bl[4];
                ldsm_x4(bh, boff);        // Ch
                ldsm_x4(bl, boff + 64);   // Cl
#pragma unroll
                for (int mt = 0; mt < 2; ++mt) {
                    float d[4] = {0.f, 0.f, 0.f, 0.f};
                    mma16816h(d, afr[mt][0], bh[0], bh[1]);   // S.Ch lo-j
                    mma16816h(d, afr[mt][1], bh[2], bh[3]);   // S.Ch hi-j
                    mma16816h(d, afr[mt][0], bl[0], bl[1]);   // S.Cl lo-j
                    mma16816h(d, afr[mt][1], bl[2], bl[3]);   // S.Cl hi-j
                    if (mt == 0) {
                        yA0 = fmaf(d[0], hreg[0][it][0], fmaf(d[1], hreg[0][it][1], yA0));
                        yB0 = fmaf(d[2], hreg[0][it][2], fmaf(d[3], hreg[0][it][3], yB0));
                    } else {
                        yA1 = fmaf(d[0], hreg[1][it][0], fmaf(d[1], hreg[1][it][1], yA1));
                        yB1 = fmaf(d[2], hreg[1][it][2], fmaf(d[3], hreg[1][it][3], yB1));
                    }
                }
            }
#pragma unroll
            for (int o = 1; o <= 2; o <<= 1) {
                yA0 += __shfl_xor_sync(0xffffffffu, yA0, o);
                yB0 += __shfl_xor_sync(0xffffffffu, yB0, o);
                yA1 += __shfl_xor_sync(0xffffffffu, yA1, o);
                yB1 += __shfl_xor_sync(0xffffffffu, yB1, o);
            }
            if (tg == (k & 3)) {
                const int mrA = (wid * 2) * 16, mrB = (wid * 2 + 1) * 16;
                ys[(mrA + g) * 33 + k] = yA0;
                ys[(mrA + g + 8) * 33 + k] = yB0;
                ys[(mrB + g) * 33 + k] = yA1;
                ys[(mrB + g + 8) * 33 + k] = yB1;
            }
        }
    }
    __syncthreads();

    // residual (re-read g_h from L2) + coalesced store
#pragma unroll
    for (int p = 0; p < 8; ++p) {
        const int idx = tid + p * 256;
        const int r = idx >> 3, c = (idx & 7) * 4;
        const float4 hv = *reinterpret_cast<const float4*>(
            &g_h[(size_t)(tok0 + r) * 512 + head * 32 + c]);
        float4 v;
        v.x = ys[r * 33 + c + 0] + hv.x;
        v.y = ys[r * 33 + c + 1] + hv.y;
        v.z = ys[r * 33 + c + 2] + hv.z;
        v.w = ys[r * 33 + c + 3] + hv.w;
        *reinterpret_cast<float4*>(
            &g_y[(size_t)(tok0 + r) * 512 + head * 32 + c]) = v;
    }
}

// ---------------------------------------------------------------------------
// K4: LayerNorm
// ---------------------------------------------------------------------------
__global__ __launch_bounds__(256) void ln_kernel(const float* __restrict__ gamma,
                                                 const float* __restrict__ beta,
                                                 float* __restrict__ out) {
    const int w = threadIdx.x >> 5, lane = threadIdx.x & 31;
    const int token = blockIdx.x * 8 + w;
    const float* yp = g_y + (size_t)token * En;
    float vals[16], sum = 0.f, sq = 0.f;
#pragma unroll
    for (int c2 = 0; c2 < 16; ++c2) {
        const float v = yp[c2 * 32 + lane];
        vals[c2] = v; sum += v; sq = fmaf(v, v, sq);
    }
#pragma unroll
    for (int o = 16; o; o >>= 1) {
        sum += __shfl_xor_sync(0xffffffffu, sum, o);
        sq += __shfl_xor_sync(0xffffffffu, sq, o);
    }
    const float mu = sum * (1.f / 512.f);
    const float var = sq * (1.f / 512.f) - mu * mu;
    const float inv = rsqrtf(var + LN_EPS);
    float* op = out + (size_t)token * En;
#pragma unroll
    for (int c2 = 0; c2 < 16; ++c2) {
        const int e = c2 * 32 + lane;
        op[e] = (vals[c2] - mu) * inv * gamma[e] + beta[e];
    }
}

// ---------------------------------------------------------------------------
extern "C" void kernel_launch(void* const* d_in, const int* in_sizes, int n_in,
                              void* d_out, int out_size) {
    const float* x = (const float*)d_in[0];
    const float* W = (const float*)d_in[1];
    const float* bias = (const float*)d_in[2];
    const float* cmap = (const float*)d_in[3];
    const float* gamma = (const float*)d_in[4];
    const float* beta = (const float*)d_in[5];
    float* out = (float*)d_out;

    static int smem_set = 0;
    if (!smem_set) {
        cudaFuncSetAttribute(bilinear_mma_kernel,
                             cudaFuncAttributeMaxDynamicSharedMemorySize, SM_TOTAL);
        cudaFuncSetAttribute(gemm_mma_kernel,
                             cudaFuncAttributeMaxDynamicSharedMemorySize, G_TOTAL);
        smem_set = 1;
    }

    cpack_kernel<<<64, 256>>>(cmap);
    wpack_kernel<<<128, 256>>>(W);
    gemm_mma_kernel<<<dim3(4, 128), 256, G_TOTAL>>>(x, bias);
    scan_local_kernel<<<NCHUNK * NCH / 256, 256>>>();
    scan_emit_kernel<<<NCHUNK * NCH / 256, 256>>>();
    bilinear_mma_kernel<<<dim3(64, Hn), 256, SM_TOTAL>>>();
    ln_kernel<<<BT / 8, 256>>>(gamma, beta, out);
}

// round 11
// speedup vs baseline: 1.2501x; 1.0564x over previous
#include <cuda_runtime.h>
#include <cuda_bf16.h>
#include <cuda_fp16.h>
#include <cstdint>

// ConceptLayer: h = xW+b ; S = decayed scan ; y = bilinear(h,S;C)+h ; LayerNorm
// B=8 T=2048 E=512 H=16 D=32.  sm_100-safe: mma.sync (HMMA), cp.async, ldmatrix.
#define Bn 8
#define Tn 2048
#define En 512
#define Hn 16
#define BT (Bn * Tn)
#define LN_EPS 1e-3f
#define INV_DECAY (1.0f / 1.2f)
#define CHUNK 128
#define NCHUNK (Tn / CHUNK)
#define NCH (Bn * En)
#define WPITCH 520

__device__ float g_h[BT * En];
__device__ float g_S[BT * En];
__device__ float g_y[BT * En];
__device__ float g_local[NCHUNK * NCH];
// C packed split-fp16: [head][n=k*32+i][72 fp16] = [Ch | Cl | pad]
__device__ uint4 g_Cpack[Hn * 1024 * 9];
// W packed transposed split-fp16: [n][k] pitch 520
__device__ __half g_Wh[512 * WPITCH];
__device__ __half g_Wl[512 * WPITCH];

__device__ __forceinline__ uint32_t smem_u32(const void* p) {
    uint32_t a;
    asm("{ .reg .u64 t; cvta.to.shared.u64 t, %1; cvt.u32.u64 %0, t; }" : "=r"(a) : "l"(p));
    return a;
}
// fp16 MMA
__device__ __forceinline__ void mma16816h(float* d, const uint32_t* a, uint32_t b0, uint32_t b1) {
    asm volatile(
        "mma.sync.aligned.m16n8k16.row.col.f32.f16.f16.f32 "
        "{%0,%1,%2,%3}, {%4,%5,%6,%7}, {%8,%9}, {%0,%1,%2,%3};"
        : "+f"(d[0]), "+f"(d[1]), "+f"(d[2]), "+f"(d[3])
        : "r"(a[0]), "r"(a[1]), "r"(a[2]), "r"(a[3]), "r"(b0), "r"(b1));
}
__device__ __forceinline__ void ldsm_x2(uint32_t& r0, uint32_t& r1, uint32_t addr) {
    asm volatile("ldmatrix.sync.aligned.m8n8.x2.shared.b16 {%0,%1}, [%2];"
                 : "=r"(r0), "=r"(r1) : "r"(addr));
}
__device__ __forceinline__ void ldsm_x4(uint32_t* r, uint32_t addr) {
    asm volatile("ldmatrix.sync.aligned.m8n8.x4.shared.b16 {%0,%1,%2,%3}, [%4];"
                 : "=r"(r[0]), "=r"(r[1]), "=r"(r[2]), "=r"(r[3]) : "r"(addr));
}
__device__ __forceinline__ void cp_async16(uint32_t dst, const void* src) {
    asm volatile("cp.async.cg.shared.global [%0], [%1], 16;" :: "r"(dst), "l"(src) : "memory");
}

// ---------------------------------------------------------------------------
// K0a: pack C -> split fp16 [head][n][72] = [Ch(32) | Cl(32) | pad(8)]
// ---------------------------------------------------------------------------
__global__ void cpack_kernel(const float* __restrict__ C) {
    const int idx = blockIdx.x * 256 + threadIdx.x;
    const float* src = C + (size_t)idx * 32;
    unsigned short hi[32], lo[32];
#pragma unroll
    for (int j = 0; j < 32; ++j) {
        const float v = src[j];
        const __half h = __float2half(v);
        hi[j] = __half_as_ushort(h);
        lo[j] = __half_as_ushort(__float2half(v - __half2float(h)));
    }
    uint4* dst = g_Cpack + (size_t)idx * 9;
#pragma unroll
    for (int q = 0; q < 4; ++q) {
        uint4 v;
        v.x = (uint32_t)hi[q * 8 + 0] | ((uint32_t)hi[q * 8 + 1] << 16);
        v.y = (uint32_t)hi[q * 8 + 2] | ((uint32_t)hi[q * 8 + 3] << 16);
        v.z = (uint32_t)hi[q * 8 + 4] | ((uint32_t)hi[q * 8 + 5] << 16);
        v.w = (uint32_t)hi[q * 8 + 6] | ((uint32_t)hi[q * 8 + 7] << 16);
        dst[q] = v;
        uint4 w;
        w.x = (uint32_t)lo[q * 8 + 0] | ((uint32_t)lo[q * 8 + 1] << 16);
        w.y = (uint32_t)lo[q * 8 + 2] | ((uint32_t)lo[q * 8 + 3] << 16);
        w.z = (uint32_t)lo[q * 8 + 4] | ((uint32_t)lo[q * 8 + 5] << 16);
        w.w = (uint32_t)lo[q * 8 + 6] | ((uint32_t)lo[q * 8 + 7] << 16);
        dst[4 + q] = w;
    }
}

// ---------------------------------------------------------------------------
// K0b: pack W [k][n] f32 -> g_Wh/g_Wl [n][k] fp16 split, pitch WPITCH
// ---------------------------------------------------------------------------
__global__ void wpack_kernel(const float* __restrict__ W) {
    const int n = (blockIdx.x & 1) * 256 + threadIdx.x;
    const int k0 = (blockIdx.x >> 1) * 8;
    unsigned short hi[8], lo[8];
#pragma unroll
    for (int u = 0; u < 8; ++u) {
        const float v = W[(size_t)(k0 + u) * 512 + n];
        const __half h = __float2half(v);
        hi[u] = __half_as_ushort(h);
        lo[u] = __half_as_ushort(__float2half(v - __half2float(h)));
    }
    uint4 vh, vl;
    vh.x = (uint32_t)hi[0] | ((uint32_t)hi[1] << 16);
    vh.y = (uint32_t)hi[2] | ((uint32_t)hi[3] << 16);
    vh.z = (uint32_t)hi[4] | ((uint32_t)hi[5] << 16);
    vh.w = (uint32_t)hi[6] | ((uint32_t)hi[7] << 16);
    vl.x = (uint32_t)lo[0] | ((uint32_t)lo[1] << 16);
    vl.y = (uint32_t)lo[2] | ((uint32_t)lo[3] << 16);
    vl.z = (uint32_t)lo[4] | ((uint32_t)lo[5] << 16);
    vl.w = (uint32_t)lo[6] | ((uint32_t)lo[7] << 16);
    *reinterpret_cast<uint4*>(&g_Wh[(size_t)n * WPITCH + k0]) = vh;
    *reinterpret_cast<uint4*>(&g_Wl[(size_t)n * WPITCH + k0]) = vl;
}

// ---------------------------------------------------------------------------
// K1: h = x @ W + b via mma.sync fp16 asymmetric split:
// x single fp16, W hi/lo -> 2 combos (x.Wh + x.Wl), 128 MMA/chunk (was 192).
// ---------------------------------------------------------------------------
#define G_AH 0
#define G_BH 18432
#define G_BL 36864
#define G_TOTAL 55296

__global__ __launch_bounds__(256, 2) void gemm_mma_kernel(
    const float* __restrict__ x, const float* __restrict__ bias) {
    extern __shared__ char smem[];
    const uint32_t sb = smem_u32(smem);
    const int tid = threadIdx.x;
    const int wid = tid >> 5, lane = tid & 31;
    const int g = lane >> 2, tg = lane & 3;
    const int mw = wid & 3, nw = wid >> 2;
    const int gm0 = blockIdx.y * 128;
    const int gn0 = blockIdx.x * 128;

    float acc[2][8][4];
#pragma unroll
    for (int mt = 0; mt < 2; ++mt)
#pragma unroll
        for (int nt = 0; nt < 8; ++nt)
#pragma unroll
            for (int e = 0; e < 4; ++e) acc[mt][nt][e] = 0.f;

    const int xm = tid >> 1, xh4 = (tid & 1) * 32;
    const uint32_t a_h_dst = sb + G_AH + xm * 144 + xh4 * 2;
    const int brow = tid >> 3, bseg = (tid & 7) * 8;

    for (int kc = 0; kc < 8; ++kc) {
#pragma unroll
        for (int it = 0; it < 4; ++it) {
            const int row = brow + it * 32;
            cp_async16(sb + G_BH + row * 144 + bseg * 2,
                       &g_Wh[(size_t)(gn0 + row) * WPITCH + kc * 64 + bseg]);
            cp_async16(sb + G_BL + row * 144 + bseg * 2,
                       &g_Wl[(size_t)(gn0 + row) * WPITCH + kc * 64 + bseg]);
        }
        asm volatile("cp.async.commit_group;" ::: "memory");
        {
            const float4* xs = reinterpret_cast<const float4*>(
                x + (size_t)(gm0 + xm) * 512 + kc * 64 + xh4);
            unsigned short sh[32];
#pragma unroll
            for (int q = 0; q < 8; ++q) {
                float4 v = xs[q];
                sh[q * 4 + 0] = __half_as_ushort(__float2half(v.x));
                sh[q * 4 + 1] = __half_as_ushort(__float2half(v.y));
                sh[q * 4 + 2] = __half_as_ushort(__float2half(v.z));
                sh[q * 4 + 3] = __half_as_ushort(__float2half(v.w));
            }
#pragma unroll
            for (int q = 0; q < 4; ++q) {
                uint4 v;
                v.x = (uint32_t)sh[q * 8 + 0] | ((uint32_t)sh[q * 8 + 1] << 16);
                v.y = (uint32_t)sh[q * 8 + 2] | ((uint32_t)sh[q * 8 + 3] << 16);
                v.z = (uint32_t)sh[q * 8 + 4] | ((uint32_t)sh[q * 8 + 5] << 16);
                v.w = (uint32_t)sh[q * 8 + 6] | ((uint32_t)sh[q * 8 + 7] << 16);
                *reinterpret_cast<uint4*>(smem + (a_h_dst - sb) + q * 16) = v;
            }
        }
        asm volatile("cp.async.wait_group 0;" ::: "memory");
        __syncthreads();

        const uint32_t bb = sb + (lane & 7) * 144 + ((lane >> 3) & 1) * 16 +
                            (nw * 64) * 144;
#pragma unroll
        for (int s = 0; s < 4; ++s) {
            uint32_t ah[2][4];
#pragma unroll
            for (int mt = 0; mt < 2; ++mt) {
                const int mr = mw * 32 + mt * 16;
                const uint32_t ra = (mr + g) * 144 + (s * 16 + tg * 2) * 2;
                const uint32_t rb = (mr + g + 8) * 144 + (s * 16 + tg * 2) * 2;
                ah[mt][0] = *reinterpret_cast<const uint32_t*>(smem + G_AH + ra);
                ah[mt][1] = *reinterpret_cast<const uint32_t*>(smem + G_AH + rb);
                ah[mt][2] = *reinterpret_cast<const uint32_t*>(smem + G_AH + ra + 16);
                ah[mt][3] = *reinterpret_cast<const uint32_t*>(smem + G_AH + rb + 16);
            }
#pragma unroll
            for (int nt = 0; nt < 8; ++nt) {
                uint32_t bh0, bh1, bl0, bl1;
                const uint32_t bo = bb + nt * 8 * 144 + s * 32;
                ldsm_x2(bh0, bh1, bo + G_BH);
                ldsm_x2(bl0, bl1, bo + G_BL);
#pragma unroll
                for (int mt = 0; mt < 2; ++mt) {
                    mma16816h(acc[mt][nt], ah[mt], bh0, bh1);
                    mma16816h(acc[mt][nt], ah[mt], bl0, bl1);
                }
            }
        }
        __syncthreads();
    }
#pragma unroll
    for (int nt = 0; nt < 8; ++nt) {
        const int col = gn0 + nw * 64 + nt * 8 + tg * 2;
        const float b0 = __ldg(&bias[col]), b1 = __ldg(&bias[col + 1]);
#pragma unroll
        for (int mt = 0; mt < 2; ++mt) {
            const int row = gm0 + mw * 32 + mt * 16 + g;
            float2 v0 = {acc[mt][nt][0] + b0, acc[mt][nt][1] + b1};
            float2 v1 = {acc[mt][nt][2] + b0, acc[mt][nt][3] + b1};
            *reinterpret_cast<float2*>(&g_h[(size_t)row * 512 + col]) = v0;
            *reinterpret_cast<float2*>(&g_h[(size_t)(row + 8) * 512 + col]) = v1;
        }
    }
}

// ---------------------------------------------------------------------------
// K2: decayed scan — batched loads for MLP
// ---------------------------------------------------------------------------
__global__ void scan_local_kernel() {
    const int tid = blockIdx.x * blockDim.x + threadIdx.x;
    const int m = tid >> 12, c = tid & 4095;
    const int b = c >> 9, hd = c & 511;
    const float* hp = g_h + (size_t)(b * Tn + m * CHUNK) * En + hd;
    float s = 0.f;
    for (int t0 = 0; t0 < CHUNK; t0 += 8) {
        float buf[8];
#pragma unroll
        for (int u = 0; u < 8; ++u) buf[u] = hp[(size_t)(t0 + u) * En];
#pragma unroll
        for (int u = 0; u < 8; ++u) s = (s + buf[u]) * INV_DECAY;
    }
    g_local[m * NCH + c] = s;
}
__global__ void scan_emit_kernel() {
    const int tid = blockIdx.x * blockDim.x + threadIdx.x;
    const int m = tid >> 12, c = tid & 4095;
    const int b = c >> 9, hd = c & 511;
    float r = 1.f;
#pragma unroll
    for (int q = 0; q < CHUNK; ++q) r *= INV_DECAY;
    float s = 0.f;
    for (int mm = 0; mm < m; ++mm) s = s * r + g_local[mm * NCH + c];
    const float* hp = g_h + (size_t)(b * Tn + m * CHUNK) * En + hd;
    float* Sp = g_S + (size_t)(b * Tn + m * CHUNK) * En + hd;
    for (int t0 = 0; t0 < CHUNK; t0 += 8) {
        float buf[8], sv[8];
#pragma unroll
        for (int u = 0; u < 8; ++u) buf[u] = hp[(size_t)(t0 + u) * En];
#pragma unroll
        for (int u = 0; u < 8; ++u) {
            sv[u] = s;
            s = (s + buf[u]) * INV_DECAY;
        }
#pragma unroll
        for (int u = 0; u < 8; ++u) Sp[(size_t)(t0 + u) * En] = sv[u];
    }
}

// ---------------------------------------------------------------------------
// K3: bilinear via mma.sync fp16 (S single, C hi/lo -> 2 combos = 8 MMA/it).
// 256 tokens/block, 8 warps x 2 m-tiles; C frags via ldmatrix.x4. (R10 winner)
// ---------------------------------------------------------------------------
#define SM_A 0            // 256*80   = 20480
#define SM_B 20480        // 1024*144 = 147456
#define SM_Y 167936       // 256*33*4 = 33792
#define SM_TOTAL 201728

__global__ __launch_bounds__(256, 1) void bilinear_mma_kernel() {
    extern __shared__ char smem[];
    const uint32_t sb = smem_u32(smem);
    const int tid = threadIdx.x;
    const int wid = tid >> 5, lane = tid & 31;
    const int head = blockIdx.y;
    const int tok0 = blockIdx.x * 256;
    float* ys = reinterpret_cast<float*>(smem + SM_Y);

    // C prefetch FIRST (hidden behind A pack)
    {
        const uint4* gsrc = g_Cpack + (size_t)head * 9216;
#pragma unroll
        for (int t = 0; t < 36; ++t) {
            const int gidx = tid + t * 256;
            cp_async16(sb + SM_B + gidx * 16, gsrc + gidx);
        }
        asm volatile("cp.async.commit_group;" ::: "memory");
    }

    // A pack: each thread packs one of 256 rows (S -> fp16 single)
    {
        const int r = tid;
        const float* Sp = &g_S[(size_t)(tok0 + r) * 512 + head * 32];
        unsigned short sh[32];
#pragma unroll
        for (int q = 0; q < 8; ++q) {
            float4 v = *reinterpret_cast<const float4*>(Sp + q * 4);
            sh[q * 4 + 0] = __half_as_ushort(__float2half(v.x));
            sh[q * 4 + 1] = __half_as_ushort(__float2half(v.y));
            sh[q * 4 + 2] = __half_as_ushort(__float2half(v.z));
            sh[q * 4 + 3] = __half_as_ushort(__float2half(v.w));
        }
        uint4* arow = reinterpret_cast<uint4*>(smem + SM_A + r * 80);
#pragma unroll
        for (int q = 0; q < 4; ++q) {
            uint4 v;
            v.x = (uint32_t)sh[q * 8 + 0] | ((uint32_t)sh[q * 8 + 1] << 16);
            v.y = (uint32_t)sh[q * 8 + 2] | ((uint32_t)sh[q * 8 + 3] << 16);
            v.z = (uint32_t)sh[q * 8 + 4] | ((uint32_t)sh[q * 8 + 5] << 16);
            v.w = (uint32_t)sh[q * 8 + 6] | ((uint32_t)sh[q * 8 + 7] << 16);
            arow[q] = v;
        }
    }
    asm volatile("cp.async.wait_group 0;" ::: "memory");
    __syncthreads();

    {
        const int g = lane >> 2, tg = lane & 3;
        uint32_t afr[2][2][4];
        float hreg[2][4][4];
#pragma unroll
        for (int mt = 0; mt < 2; ++mt) {
            const int mr = (wid * 2 + mt) * 16;
#pragma unroll
            for (int s = 0; s < 2; ++s) {
                const char* base = smem + SM_A;
                const uint32_t ra = (mr + g) * 80 + s * 32 + tg * 4;
                const uint32_t rb = (mr + g + 8) * 80 + s * 32 + tg * 4;
                afr[mt][s][0] = *reinterpret_cast<const uint32_t*>(base + ra);
                afr[mt][s][1] = *reinterpret_cast<const uint32_t*>(base + rb);
                afr[mt][s][2] = *reinterpret_cast<const uint32_t*>(base + ra + 16);
                afr[mt][s][3] = *reinterpret_cast<const uint32_t*>(base + rb + 16);
            }
#pragma unroll
            for (int it = 0; it < 4; ++it) {
                const int i0 = it * 8 + tg * 2;
                float2 va = *reinterpret_cast<const float2*>(
                    &g_h[(size_t)(tok0 + mr + g) * 512 + head * 32 + i0]);
                float2 vb = *reinterpret_cast<const float2*>(
                    &g_h[(size_t)(tok0 + mr + g + 8) * 512 + head * 32 + i0]);
                hreg[mt][it][0] = va.x; hreg[mt][it][1] = va.y;
                hreg[mt][it][2] = vb.x; hreg[mt][it][3] = vb.y;
            }
        }
        const uint32_t bb4 = sb + SM_B + (lane & 7) * 144 + ((lane >> 3) & 3) * 16;

        for (int k = 0; k < 32; ++k) {
            float yA0 = 0.f, yB0 = 0.f, yA1 = 0.f, yB1 = 0.f;
#pragma unroll
            for (int it = 0; it < 4; ++it) {
                const uint32_t boff = bb4 + (uint32_t)(k * 32 + it * 8) * 144;
                uint32_t bh[4], bl[4];
                ldsm_x4(bh, boff);        // Ch
                ldsm_x4(bl, boff + 64);   // Cl
#pragma unroll
                for (int mt = 0; mt < 2; ++mt) {
                    float d[4] = {0.f, 0.f, 0.f, 0.f};
                    mma16816h(d, afr[mt][0], bh[0], bh[1]);   // S.Ch lo-j
                    mma16816h(d, afr[mt][1], bh[2], bh[3]);   // S.Ch hi-j
                    mma16816h(d, afr[mt][0], bl[0], bl[1]);   // S.Cl lo-j
                    mma16816h(d, afr[mt][1], bl[2], bl[3]);   // S.Cl hi-j
                    if (mt == 0) {
                        yA0 = fmaf(d[0], hreg[0][it][0], fmaf(d[1], hreg[0][it][1], yA0));
                        yB0 = fmaf(d[2], hreg[0][it][2], fmaf(d[3], hreg[0][it][3], yB0));
                    } else {
                        yA1 = fmaf(d[0], hreg[1][it][0], fmaf(d[1], hreg[1][it][1], yA1));
                        yB1 = fmaf(d[2], hreg[1][it][2], fmaf(d[3], hreg[1][it][3], yB1));
                    }
                }
            }
#pragma unroll
            for (int o = 1; o <= 2; o <<= 1) {
                yA0 += __shfl_xor_sync(0xffffffffu, yA0, o);
                yB0 += __shfl_xor_sync(0xffffffffu, yB0, o);
                yA1 += __shfl_xor_sync(0xffffffffu, yA1, o);
                yB1 += __shfl_xor_sync(0xffffffffu, yB1, o);
            }
            if (tg == (k & 3)) {
                const int mrA = (wid * 2) * 16, mrB = (wid * 2 + 1) * 16;
                ys[(mrA + g) * 33 + k] = yA0;
                ys[(mrA + g + 8) * 33 + k] = yB0;
                ys[(mrB + g) * 33 + k] = yA1;
                ys[(mrB + g + 8) * 33 + k] = yB1;
            }
        }
    }
    __syncthreads();

    // residual (re-read g_h from L2) + coalesced store
#pragma unroll
    for (int p = 0; p < 8; ++p) {
        const int idx = tid + p * 256;
        const int r = idx >> 3, c = (idx & 7) * 4;
        const float4 hv = *reinterpret_cast<const float4*>(
            &g_h[(size_t)(tok0 + r) * 512 + head * 32 + c]);
        float4 v;
        v.x = ys[r * 33 + c + 0] + hv.x;
        v.y = ys[r * 33 + c + 1] + hv.y;
        v.z = ys[r * 33 + c + 2] + hv.z;
        v.w = ys[r * 33 + c + 3] + hv.w;
        *reinterpret_cast<float4*>(
            &g_y[(size_t)(tok0 + r) * 512 + head * 32 + c]) = v;
    }
}

// ---------------------------------------------------------------------------
// K4: LayerNorm
// ---------------------------------------------------------------------------
__global__ __launch_bounds__(256) void ln_kernel(const float* __restrict__ gamma,
                                                 const float* __restrict__ beta,
                                                 float* __restrict__ out) {
    const int w = threadIdx.x >> 5, lane = threadIdx.x & 31;
    const int token = blockIdx.x * 8 + w;
    const float* yp = g_y + (size_t)token * En;
    float vals[16], sum = 0.f, sq = 0.f;
#pragma unroll
    for (int c2 = 0; c2 < 16; ++c2) {
        const float v = yp[c2 * 32 + lane];
        vals[c2] = v; sum += v; sq = fmaf(v, v, sq);
    }
#pragma unroll
    for (int o = 16; o; o >>= 1) {
        sum += __shfl_xor_sync(0xffffffffu, sum, o);
        sq += __shfl_xor_sync(0xffffffffu, sq, o);
    }
    const float mu = sum * (1.f / 512.f);
    const float var = sq * (1.f / 512.f) - mu * mu;
    const float inv = rsqrtf(var + LN_EPS);
    float* op = out + (size_t)token * En;
#pragma unroll
    for (int c2 = 0; c2 < 16; ++c2) {
        const int e = c2 * 32 + lane;
        op[e] = (vals[c2] - mu) * inv * gamma[e] + beta[e];
    }
}

// ---------------------------------------------------------------------------
extern "C" void kernel_launch(void* const* d_in, const int* in_sizes, int n_in,
                              void* d_out, int out_size) {
    const float* x = (const float*)d_in[0];
    const float* W = (const float*)d_in[1];
    const float* bias = (const float*)d_in[2];
    const float* cmap = (const float*)d_in[3];
    const float* gamma = (const float*)d_in[4];
    const float* beta = (const float*)d_in[5];
    float* out = (float*)d_out;

    static int smem_set = 0;
    if (!smem_set) {
        cudaFuncSetAttribute(bilinear_mma_kernel,
                             cudaFuncAttributeMaxDynamicSharedMemorySize, SM_TOTAL);
        cudaFuncSetAttribute(gemm_mma_kernel,
                             cudaFuncAttributeMaxDynamicSharedMemorySize, G_TOTAL);
        smem_set = 1;
    }

    cpack_kernel<<<64, 256>>>(cmap);
    wpack_kernel<<<128, 256>>>(W);
    gemm_mma_kernel<<<dim3(4, 128), 256, G_TOTAL>>>(x, bias);
    scan_local_kernel<<<NCHUNK * NCH / 256, 256>>>();
    scan_emit_kernel<<<NCHUNK * NCH / 256, 256>>>();
    bilinear_mma_kernel<<<dim3(64, Hn), 256, SM_TOTAL>>>();
    ln_kernel<<<BT / 8, 256>>>(gamma, beta, out);
}

// round 12
// speedup vs baseline: 1.5127x; 1.2100x over previous
#include <cuda_runtime.h>
#include <cuda_bf16.h>
#include <cuda_fp16.h>
#include <cstdint>

// ConceptLayer: h = xW+b ; S = decayed scan ; y = bilinear(h,S;C)+h ; LayerNorm
// B=8 T=2048 E=512 H=16 D=32.  sm_100-safe: mma.sync (HMMA), cp.async, ldmatrix.
#define Bn 8
#define Tn 2048
#define En 512
#define Hn 16
#define BT (Bn * Tn)
#define LN_EPS 1e-3f
#define INV_DECAY (1.0f / 1.2f)
#define CHUNK 128
#define NCHUNK (Tn / CHUNK)
#define NCH (Bn * En)
#define WPITCH 520

__device__ float g_h[BT * En];
__device__ float g_S[BT * En];
__device__ float g_y[BT * En];
__device__ float g_local[NCHUNK * NCH];
// C packed fp16 (single precision level): [head][n=k*32+i][40 fp16 pitch]
// = [C(j 0..31) | pad(8)], 80B rows, 5 uint4/row (5th never read by ldsm)
__device__ uint4 g_Cpack[Hn * 1024 * 5];
// W packed transposed split-fp16: [n][k] pitch 520
__device__ __half g_Wh[512 * WPITCH];
__device__ __half g_Wl[512 * WPITCH];

__device__ __forceinline__ uint32_t smem_u32(const void* p) {
    uint32_t a;
    asm("{ .reg .u64 t; cvta.to.shared.u64 t, %1; cvt.u32.u64 %0, t; }" : "=r"(a) : "l"(p));
    return a;
}
// fp16 MMA
__device__ __forceinline__ void mma16816h(float* d, const uint32_t* a, uint32_t b0, uint32_t b1) {
    asm volatile(
        "mma.sync.aligned.m16n8k16.row.col.f32.f16.f16.f32 "
        "{%0,%1,%2,%3}, {%4,%5,%6,%7}, {%8,%9}, {%0,%1,%2,%3};"
        : "+f"(d[0]), "+f"(d[1]), "+f"(d[2]), "+f"(d[3])
        : "r"(a[0]), "r"(a[1]), "r"(a[2]), "r"(a[3]), "r"(b0), "r"(b1));
}
__device__ __forceinline__ void ldsm_x2(uint32_t& r0, uint32_t& r1, uint32_t addr) {
    asm volatile("ldmatrix.sync.aligned.m8n8.x2.shared.b16 {%0,%1}, [%2];"
                 : "=r"(r0), "=r"(r1) : "r"(addr));
}
__device__ __forceinline__ void ldsm_x4(uint32_t* r, uint32_t addr) {
    asm volatile("ldmatrix.sync.aligned.m8n8.x4.shared.b16 {%0,%1,%2,%3}, [%4];"
                 : "=r"(r[0]), "=r"(r[1]), "=r"(r[2]), "=r"(r[3]) : "r"(addr));
}
__device__ __forceinline__ void cp_async16(uint32_t dst, const void* src) {
    asm volatile("cp.async.cg.shared.global [%0], [%1], 16;" :: "r"(dst), "l"(src) : "memory");
}

// ---------------------------------------------------------------------------
// K0a: pack C -> fp16 [head][n][40] (single level, 80B pitch)
// ---------------------------------------------------------------------------
__global__ void cpack_kernel(const float* __restrict__ C) {
    const int idx = blockIdx.x * 256 + threadIdx.x;
    const float* src = C + (size_t)idx * 32;
    unsigned short hi[32];
#pragma unroll
    for (int j = 0; j < 32; ++j) hi[j] = __half_as_ushort(__float2half(src[j]));
    uint4* dst = g_Cpack + (size_t)idx * 5;
#pragma unroll
    for (int q = 0; q < 4; ++q) {
        uint4 v;
        v.x = (uint32_t)hi[q * 8 + 0] | ((uint32_t)hi[q * 8 + 1] << 16);
        v.y = (uint32_t)hi[q * 8 + 2] | ((uint32_t)hi[q * 8 + 3] << 16);
        v.z = (uint32_t)hi[q * 8 + 4] | ((uint32_t)hi[q * 8 + 5] << 16);
        v.w = (uint32_t)hi[q * 8 + 6] | ((uint32_t)hi[q * 8 + 7] << 16);
        dst[q] = v;
    }
    dst[4] = make_uint4(0u, 0u, 0u, 0u);   // pad (never read by ldsm)
}

// ---------------------------------------------------------------------------
// K0b: pack W [k][n] f32 -> g_Wh/g_Wl [n][k] fp16 split, pitch WPITCH
// ---------------------------------------------------------------------------
__global__ void wpack_kernel(const float* __restrict__ W) {
    const int n = (blockIdx.x & 1) * 256 + threadIdx.x;
    const int k0 = (blockIdx.x >> 1) * 8;
    unsigned short hi[8], lo[8];
#pragma unroll
    for (int u = 0; u < 8; ++u) {
        const float v = W[(size_t)(k0 + u) * 512 + n];
        const __half h = __float2half(v);
        hi[u] = __half_as_ushort(h);
        lo[u] = __half_as_ushort(__float2half(v - __half2float(h)));
    }
    uint4 vh, vl;
    vh.x = (uint32_t)hi[0] | ((uint32_t)hi[1] << 16);
    vh.y = (uint32_t)hi[2] | ((uint32_t)hi[3] << 16);
    vh.z = (uint32_t)hi[4] | ((uint32_t)hi[5] << 16);
    vh.w = (uint32_t)hi[6] | ((uint32_t)hi[7] << 16);
    vl.x = (uint32_t)lo[0] | ((uint32_t)lo[1] << 16);
    vl.y = (uint32_t)lo[2] | ((uint32_t)lo[3] << 16);
    vl.z = (uint32_t)lo[4] | ((uint32_t)lo[5] << 16);
    vl.w = (uint32_t)lo[6] | ((uint32_t)lo[7] << 16);
    *reinterpret_cast<uint4*>(&g_Wh[(size_t)n * WPITCH + k0]) = vh;
    *reinterpret_cast<uint4*>(&g_Wl[(size_t)n * WPITCH + k0]) = vl;
}

// ---------------------------------------------------------------------------
// K1: h = x @ W + b via mma.sync fp16 asymmetric split (R11 winner, unchanged)
// ---------------------------------------------------------------------------
#define G_AH 0
#define G_BH 18432
#define G_BL 36864
#define G_TOTAL 55296

__global__ __launch_bounds__(256, 2) void gemm_mma_kernel(
    const float* __restrict__ x, const float* __restrict__ bias) {
    extern __shared__ char smem[];
    const uint32_t sb = smem_u32(smem);
    const int tid = threadIdx.x;
    const int wid = tid >> 5, lane = tid & 31;
    const int g = lane >> 2, tg = lane & 3;
    const int mw = wid & 3, nw = wid >> 2;
    const int gm0 = blockIdx.y * 128;
    const int gn0 = blockIdx.x * 128;

    float acc[2][8][4];
#pragma unroll
    for (int mt = 0; mt < 2; ++mt)
#pragma unroll
        for (int nt = 0; nt < 8; ++nt)
#pragma unroll
            for (int e = 0; e < 4; ++e) acc[mt][nt][e] = 0.f;

    const int xm = tid >> 1, xh4 = (tid & 1) * 32;
    const uint32_t a_h_dst = sb + G_AH + xm * 144 + xh4 * 2;
    const int brow = tid >> 3, bseg = (tid & 7) * 8;

    for (int kc = 0; kc < 8; ++kc) {
#pragma unroll
        for (int it = 0; it < 4; ++it) {
            const int row = brow + it * 32;
            cp_async16(sb + G_BH + row * 144 + bseg * 2,
                       &g_Wh[(size_t)(gn0 + row) * WPITCH + kc * 64 + bseg]);
            cp_async16(sb + G_BL + row * 144 + bseg * 2,
                       &g_Wl[(size_t)(gn0 + row) * WPITCH + kc * 64 + bseg]);
        }
        asm volatile("cp.async.commit_group;" ::: "memory");
        {
            const float4* xs = reinterpret_cast<const float4*>(
                x + (size_t)(gm0 + xm) * 512 + kc * 64 + xh4);
            unsigned short sh[32];
#pragma unroll
            for (int q = 0; q < 8; ++q) {
                float4 v = xs[q];
                sh[q * 4 + 0] = __half_as_ushort(__float2half(v.x));
                sh[q * 4 + 1] = __half_as_ushort(__float2half(v.y));
                sh[q * 4 + 2] = __half_as_ushort(__float2half(v.z));
                sh[q * 4 + 3] = __half_as_ushort(__float2half(v.w));
            }
#pragma unroll
            for (int q = 0; q < 4; ++q) {
                uint4 v;
                v.x = (uint32_t)sh[q * 8 + 0] | ((uint32_t)sh[q * 8 + 1] << 16);
                v.y = (uint32_t)sh[q * 8 + 2] | ((uint32_t)sh[q * 8 + 3] << 16);
                v.z = (uint32_t)sh[q * 8 + 4] | ((uint32_t)sh[q * 8 + 5] << 16);
                v.w = (uint32_t)sh[q * 8 + 6] | ((uint32_t)sh[q * 8 + 7] << 16);
                *reinterpret_cast<uint4*>(smem + (a_h_dst - sb) + q * 16) = v;
            }
        }
        asm volatile("cp.async.wait_group 0;" ::: "memory");
        __syncthreads();

        const uint32_t bb = sb + (lane & 7) * 144 + ((lane >> 3) & 1) * 16 +
                            (nw * 64) * 144;
#pragma unroll
        for (int s = 0; s < 4; ++s) {
            uint32_t ah[2][4];
#pragma unroll
            for (int mt = 0; mt < 2; ++mt) {
                const int mr = mw * 32 + mt * 16;
                const uint32_t ra = (mr + g) * 144 + (s * 16 + tg * 2) * 2;
                const uint32_t rb = (mr + g + 8) * 144 + (s * 16 + tg * 2) * 2;
                ah[mt][0] = *reinterpret_cast<const uint32_t*>(smem + G_AH + ra);
                ah[mt][1] = *reinterpret_cast<const uint32_t*>(smem + G_AH + rb);
                ah[mt][2] = *reinterpret_cast<const uint32_t*>(smem + G_AH + ra + 16);
                ah[mt][3] = *reinterpret_cast<const uint32_t*>(smem + G_AH + rb + 16);
            }
#pragma unroll
            for (int nt = 0; nt < 8; ++nt) {
                uint32_t bh0, bh1, bl0, bl1;
                const uint32_t bo = bb + nt * 8 * 144 + s * 32;
                ldsm_x2(bh0, bh1, bo + G_BH);
                ldsm_x2(bl0, bl1, bo + G_BL);
#pragma unroll
                for (int mt = 0; mt < 2; ++mt) {
                    mma16816h(acc[mt][nt], ah[mt], bh0, bh1);
                    mma16816h(acc[mt][nt], ah[mt], bl0, bl1);
                }
            }
        }
        __syncthreads();
    }
#pragma unroll
    for (int nt = 0; nt < 8; ++nt) {
        const int col = gn0 + nw * 64 + nt * 8 + tg * 2;
        const float b0 = __ldg(&bias[col]), b1 = __ldg(&bias[col + 1]);
#pragma unroll
        for (int mt = 0; mt < 2; ++mt) {
            const int row = gm0 + mw * 32 + mt * 16 + g;
            float2 v0 = {acc[mt][nt][0] + b0, acc[mt][nt][1] + b1};
            float2 v1 = {acc[mt][nt][2] + b0, acc[mt][nt][3] + b1};
            *reinterpret_cast<float2*>(&g_h[(size_t)row * 512 + col]) = v0;
            *reinterpret_cast<float2*>(&g_h[(size_t)(row + 8) * 512 + col]) = v1;
        }
    }
}

// ---------------------------------------------------------------------------
// K2: decayed scan — batched loads for MLP
// ---------------------------------------------------------------------------
__global__ void scan_local_kernel() {
    const int tid = blockIdx.x * blockDim.x + threadIdx.x;
    const int m = tid >> 12, c = tid & 4095;
    const int b = c >> 9, hd = c & 511;
    const float* hp = g_h + (size_t)(b * Tn + m * CHUNK) * En + hd;
    float s = 0.f;
    for (int t0 = 0; t0 < CHUNK; t0 += 8) {
        float buf[8];
#pragma unroll
        for (int u = 0; u < 8; ++u) buf[u] = hp[(size_t)(t0 + u) * En];
#pragma unroll
        for (int u = 0; u < 8; ++u) s = (s + buf[u]) * INV_DECAY;
    }
    g_local[m * NCH + c] = s;
}
__global__ void scan_emit_kernel() {
    const int tid = blockIdx.x * blockDim.x + threadIdx.x;
    const int m = tid >> 12, c = tid & 4095;
    const int b = c >> 9, hd = c & 511;
    float r = 1.f;
#pragma unroll
    for (int q = 0; q < CHUNK; ++q) r *= INV_DECAY;
    float s = 0.f;
    for (int mm = 0; mm < m; ++mm) s = s * r + g_local[mm * NCH + c];
    const float* hp = g_h + (size_t)(b * Tn + m * CHUNK) * En + hd;
    float* Sp = g_S + (size_t)(b * Tn + m * CHUNK) * En + hd;
    for (int t0 = 0; t0 < CHUNK; t0 += 8) {
        float buf[8], sv[8];
#pragma unroll
        for (int u = 0; u < 8; ++u) buf[u] = hp[(size_t)(t0 + u) * En];
#pragma unroll
        for (int u = 0; u < 8; ++u) {
            sv[u] = s;
            s = (s + buf[u]) * INV_DECAY;
        }
#pragma unroll
        for (int u = 0; u < 8; ++u) Sp[(size_t)(t0 + u) * En] = sv[u];
    }
}

// ---------------------------------------------------------------------------
// K3: bilinear via mma.sync fp16 (S single, C single -> 1 combo = 4 MMA/it).
// 256 tokens/block, 8 warps x 2 m-tiles; C frags via ldmatrix.x4, pitch 80B.
// ---------------------------------------------------------------------------
#define SM_A 0            // 256*80  = 20480
#define SM_B 20480        // 1024*80 = 81920
#define SM_Y 102400       // 256*33*4 = 33792
#define SM_TOTAL 136192

__global__ __launch_bounds__(256, 1) void bilinear_mma_kernel() {
    extern __shared__ char smem[];
    const uint32_t sb = smem_u32(smem);
    const int tid = threadIdx.x;
    const int wid = tid >> 5, lane = tid & 31;
    const int head = blockIdx.y;
    const int tok0 = blockIdx.x * 256;
    float* ys = reinterpret_cast<float*>(smem + SM_Y);

    // C prefetch FIRST (hidden behind A pack): 1024 rows x 80B = 5120 uint4
    {
        const uint4* gsrc = g_Cpack + (size_t)head * 5120;
#pragma unroll
        for (int t = 0; t < 20; ++t) {
            const int gidx = tid + t * 256;
            cp_async16(sb + SM_B + gidx * 16, gsrc + gidx);
        }
        asm volatile("cp.async.commit_group;" ::: "memory");
    }

    // A pack: each thread packs one of 256 rows (S -> fp16 single)
    {
        const int r = tid;
        const float* Sp = &g_S[(size_t)(tok0 + r) * 512 + head * 32];
        unsigned short sh[32];
#pragma unroll
        for (int q = 0; q < 8; ++q) {
            float4 v = *reinterpret_cast<const float4*>(Sp + q * 4);
            sh[q * 4 + 0] = __half_as_ushort(__float2half(v.x));
            sh[q * 4 + 1] = __half_as_ushort(__float2half(v.y));
            sh[q * 4 + 2] = __half_as_ushort(__float2half(v.z));
            sh[q * 4 + 3] = __half_as_ushort(__float2half(v.w));
        }
        uint4* arow = reinterpret_cast<uint4*>(smem + SM_A + r * 80);
#pragma unroll
        for (int q = 0; q < 4; ++q) {
            uint4 v;
            v.x = (uint32_t)sh[q * 8 + 0] | ((uint32_t)sh[q * 8 + 1] << 16);
            v.y = (uint32_t)sh[q * 8 + 2] | ((uint32_t)sh[q * 8 + 3] << 16);
            v.z = (uint32_t)sh[q * 8 + 4] | ((uint32_t)sh[q * 8 + 5] << 16);
            v.w = (uint32_t)sh[q * 8 + 6] | ((uint32_t)sh[q * 8 + 7] << 16);
            arow[q] = v;
        }
    }
    asm volatile("cp.async.wait_group 0;" ::: "memory");
    __syncthreads();

    {
        const int g = lane >> 2, tg = lane & 3;
        uint32_t afr[2][2][4];
        float hreg[2][4][4];
#pragma unroll
        for (int mt = 0; mt < 2; ++mt) {
            const int mr = (wid * 2 + mt) * 16;
#pragma unroll
            for (int s = 0; s < 2; ++s) {
                const char* base = smem + SM_A;
                const uint32_t ra = (mr + g) * 80 + s * 32 + tg * 4;
                const uint32_t rb = (mr + g + 8) * 80 + s * 32 + tg * 4;
                afr[mt][s][0] = *reinterpret_cast<const uint32_t*>(base + ra);
                afr[mt][s][1] = *reinterpret_cast<const uint32_t*>(base + rb);
                afr[mt][s][2] = *reinterpret_cast<const uint32_t*>(base + ra + 16);
                afr[mt][s][3] = *reinterpret_cast<const uint32_t*>(base + rb + 16);
            }
#pragma unroll
            for (int it = 0; it < 4; ++it) {
                const int i0 = it * 8 + tg * 2;
                float2 va = *reinterpret_cast<const float2*>(
                    &g_h[(size_t)(tok0 + mr + g) * 512 + head * 32 + i0]);
                float2 vb = *reinterpret_cast<const float2*>(
                    &g_h[(size_t)(tok0 + mr + g + 8) * 512 + head * 32 + i0]);
                hreg[mt][it][0] = va.x; hreg[mt][it][1] = va.y;
                hreg[mt][it][2] = vb.x; hreg[mt][it][3] = vb.y;
            }
        }
        const uint32_t bb4 = sb + SM_B + (lane & 7) * 80 + ((lane >> 3) & 3) * 16;

        for (int k = 0; k < 32; ++k) {
            float yA0 = 0.f, yB0 = 0.f, yA1 = 0.f, yB1 = 0.f;
#pragma unroll
            for (int it = 0; it < 4; ++it) {
                const uint32_t boff = bb4 + (uint32_t)(k * 32 + it * 8) * 80;
                uint32_t bh[4];
                ldsm_x4(bh, boff);        // C: (bh0,bh1)=j0-15, (bh2,bh3)=j16-31
#pragma unroll
                for (int mt = 0; mt < 2; ++mt) {
                    float d[4] = {0.f, 0.f, 0.f, 0.f};
                    mma16816h(d, afr[mt][0], bh[0], bh[1]);   // S.C lo-j
                    mma16816h(d, afr[mt][1], bh[2], bh[3]);   // S.C hi-j
                    if (mt == 0) {
                        yA0 = fmaf(d[0], hreg[0][it][0], fmaf(d[1], hreg[0][it][1], yA0));
                        yB0 = fmaf(d[2], hreg[0][it][2], fmaf(d[3], hreg[0][it][3], yB0));
                    } else {
                        yA1 = fmaf(d[0], hreg[1][it][0], fmaf(d[1], hreg[1][it][1], yA1));
                        yB1 = fmaf(d[2], hreg[1][it][2], fmaf(d[3], hreg[1][it][3], yB1));
                    }
                }
            }
#pragma unroll
            for (int o = 1; o <= 2; o <<= 1) {
                yA0 += __shfl_xor_sync(0xffffffffu, yA0, o);
                yB0 += __shfl_xor_sync(0xffffffffu, yB0, o);
                yA1 += __shfl_xor_sync(0xffffffffu, yA1, o);
                yB1 += __shfl_xor_sync(0xffffffffu, yB1, o);
            }
            if (tg == (k & 3)) {
                const int mrA = (wid * 2) * 16, mrB = (wid * 2 + 1) * 16;
                ys[(mrA + g) * 33 + k] = yA0;
                ys[(mrA + g + 8) * 33 + k] = yB0;
                ys[(mrB + g) * 33 + k] = yA1;
                ys[(mrB + g + 8) * 33 + k] = yB1;
            }
        }
    }
    __syncthreads();

    // residual (re-read g_h from L2) + coalesced store
#pragma unroll
    for (int p = 0; p < 8; ++p) {
        const int idx = tid + p * 256;
        const int r = idx >> 3, c = (idx & 7) * 4;
        const float4 hv = *reinterpret_cast<const float4*>(
            &g_h[(size_t)(tok0 + r) * 512 + head * 32 + c]);
        float4 v;
        v.x = ys[r * 33 + c + 0] + hv.x;
        v.y = ys[r * 33 + c + 1] + hv.y;
        v.z = ys[r * 33 + c + 2] + hv.z;
        v.w = ys[r * 33 + c + 3] + hv.w;
        *reinterpret_cast<float4*>(
            &g_y[(size_t)(tok0 + r) * 512 + head * 32 + c]) = v;
    }
}

// ---------------------------------------------------------------------------
// K4: LayerNorm
// ---------------------------------------------------------------------------
__global__ __launch_bounds__(256) void ln_kernel(const float* __restrict__ gamma,
                                                 const float* __restrict__ beta,
                                                 float* __restrict__ out) {
    const int w = threadIdx.x >> 5, lane = threadIdx.x & 31;
    const int token = blockIdx.x * 8 + w;
    const float* yp = g_y + (size_t)token * En;
    float vals[16], sum = 0.f, sq = 0.f;
#pragma unroll
    for (int c2 = 0; c2 < 16; ++c2) {
        const float v = yp[c2 * 32 + lane];
        vals[c2] = v; sum += v; sq = fmaf(v, v, sq);
    }
#pragma unroll
    for (int o = 16; o; o >>= 1) {
        sum += __shfl_xor_sync(0xffffffffu, sum, o);
        sq += __shfl_xor_sync(0xffffffffu, sq, o);
    }
    const float mu = sum * (1.f / 512.f);
    const float var = sq * (1.f / 512.f) - mu * mu;
    const float inv = rsqrtf(var + LN_EPS);
    float* op = out + (size_t)token * En;
#pragma unroll
    for (int c2 = 0; c2 < 16; ++c2) {
        const int e = c2 * 32 + lane;
        op[e] = (vals[c2] - mu) * inv * gamma[e] + beta[e];
    }
}

// ---------------------------------------------------------------------------
extern "C" void kernel_launch(void* const* d_in, const int* in_sizes, int n_in,
                              void* d_out, int out_size) {
    const float* x = (const float*)d_in[0];
    const float* W = (const float*)d_in[1];
    const float* bias = (const float*)d_in[2];
    const float* cmap = (const float*)d_in[3];
    const float* gamma = (const float*)d_in[4];
    const float* beta = (const float*)d_in[5];
    float* out = (float*)d_out;

    static int smem_set = 0;
    if (!smem_set) {
        cudaFuncSetAttribute(bilinear_mma_kernel,
                             cudaFuncAttributeMaxDynamicSharedMemorySize, SM_TOTAL);
        cudaFuncSetAttribute(gemm_mma_kernel,
                             cudaFuncAttributeMaxDynamicSharedMemorySize, G_TOTAL);
        smem_set = 1;
    }

    cpack_kernel<<<64, 256>>>(cmap);
    wpack_kernel<<<128, 256>>>(W);
    gemm_mma_kernel<<<dim3(4, 128), 256, G_TOTAL>>>(x, bias);
    scan_local_kernel<<<NCHUNK * NCH / 256, 256>>>();
    scan_emit_kernel<<<NCHUNK * NCH / 256, 256>>>();
    bilinear_mma_kernel<<<dim3(64, Hn), 256, SM_TOTAL>>>();
    ln_kernel<<<BT / 8, 256>>>(gamma, beta, out);
}

// round 13
// speedup vs baseline: 1.6864x; 1.1148x over previous
#include <cuda_runtime.h>
#include <cuda_bf16.h>
#include <cuda_fp16.h>
#include <cstdint>

// ConceptLayer: h = xW+b ; S = decayed scan ; y = bilinear(h,S;C)+h ; LayerNorm
// B=8 T=2048 E=512 H=16 D=32.  sm_100-safe: mma.sync (HMMA), cp.async, ldmatrix.
#define Bn 8
#define Tn 2048
#define En 512
#define Hn 16
#define BT (Bn * Tn)
#define LN_EPS 1e-3f
#define INV_DECAY (1.0f / 1.2f)
#define CHUNK 128
#define NCHUNK (Tn / CHUNK)
#define NCH (Bn * En)
#define WPITCH 520

__device__ float g_h[BT * En];
__device__ float g_S[BT * En];
__device__ float g_y[BT * En];
__device__ float g_local[NCHUNK * NCH];
// C packed fp16 (single precision level): [head][n=k*32+i][40 fp16 pitch]
__device__ uint4 g_Cpack[Hn * 1024 * 5];
// W packed transposed fp16 (single precision level): [n][k] pitch 520
__device__ __half g_Wh[512 * WPITCH];

__device__ __forceinline__ uint32_t smem_u32(const void* p) {
    uint32_t a;
    asm("{ .reg .u64 t; cvta.to.shared.u64 t, %1; cvt.u32.u64 %0, t; }" : "=r"(a) : "l"(p));
    return a;
}
// fp16 MMA
__device__ __forceinline__ void mma16816h(float* d, const uint32_t* a, uint32_t b0, uint32_t b1) {
    asm volatile(
        "mma.sync.aligned.m16n8k16.row.col.f32.f16.f16.f32 "
        "{%0,%1,%2,%3}, {%4,%5,%6,%7}, {%8,%9}, {%0,%1,%2,%3};"
        : "+f"(d[0]), "+f"(d[1]), "+f"(d[2]), "+f"(d[3])
        : "r"(a[0]), "r"(a[1]), "r"(a[2]), "r"(a[3]), "r"(b0), "r"(b1));
}
__device__ __forceinline__ void ldsm_x2(uint32_t& r0, uint32_t& r1, uint32_t addr) {
    asm volatile("ldmatrix.sync.aligned.m8n8.x2.shared.b16 {%0,%1}, [%2];"
                 : "=r"(r0), "=r"(r1) : "r"(addr));
}
__device__ __forceinline__ void ldsm_x4(uint32_t* r, uint32_t addr) {
    asm volatile("ldmatrix.sync.aligned.m8n8.x4.shared.b16 {%0,%1,%2,%3}, [%4];"
                 : "=r"(r[0]), "=r"(r[1]), "=r"(r[2]), "=r"(r[3]) : "r"(addr));
}
__device__ __forceinline__ void cp_async16(uint32_t dst, const void* src) {
    asm volatile("cp.async.cg.shared.global [%0], [%1], 16;" :: "r"(dst), "l"(src) : "memory");
}

// ---------------------------------------------------------------------------
// K0a: pack C -> fp16 [head][n][40] (single level, 80B pitch)
// ---------------------------------------------------------------------------
__global__ void cpack_kernel(const float* __restrict__ C) {
    const int idx = blockIdx.x * 256 + threadIdx.x;
    const float* src = C + (size_t)idx * 32;
    unsigned short hi[32];
#pragma unroll
    for (int j = 0; j < 32; ++j) hi[j] = __half_as_ushort(__float2half(src[j]));
    uint4* dst = g_Cpack + (size_t)idx * 5;
#pragma unroll
    for (int q = 0; q < 4; ++q) {
        uint4 v;
        v.x = (uint32_t)hi[q * 8 + 0] | ((uint32_t)hi[q * 8 + 1] << 16);
        v.y = (uint32_t)hi[q * 8 + 2] | ((uint32_t)hi[q * 8 + 3] << 16);
        v.z = (uint32_t)hi[q * 8 + 4] | ((uint32_t)hi[q * 8 + 5] << 16);
        v.w = (uint32_t)hi[q * 8 + 6] | ((uint32_t)hi[q * 8 + 7] << 16);
        dst[q] = v;
    }
    dst[4] = make_uint4(0u, 0u, 0u, 0u);
}

// ---------------------------------------------------------------------------
// K0b: pack W [k][n] f32 -> g_Wh [n][k] fp16 (single level), pitch WPITCH
// ---------------------------------------------------------------------------
__global__ void wpack_kernel(const float* __restrict__ W) {
    const int n = (blockIdx.x & 1) * 256 + threadIdx.x;
    const int k0 = (blockIdx.x >> 1) * 8;
    unsigned short hi[8];
#pragma unroll
    for (int u = 0; u < 8; ++u)
        hi[u] = __half_as_ushort(__float2half(W[(size_t)(k0 + u) * 512 + n]));
    uint4 vh;
    vh.x = (uint32_t)hi[0] | ((uint32_t)hi[1] << 16);
    vh.y = (uint32_t)hi[2] | ((uint32_t)hi[3] << 16);
    vh.z = (uint32_t)hi[4] | ((uint32_t)hi[5] << 16);
    vh.w = (uint32_t)hi[6] | ((uint32_t)hi[7] << 16);
    *reinterpret_cast<uint4*>(&g_Wh[(size_t)n * WPITCH + k0]) = vh;
}

// ---------------------------------------------------------------------------
// K1: h = x @ W + b via mma.sync fp16 (x single, W single -> 64 MMA/chunk)
// ---------------------------------------------------------------------------
#define G_AH 0
#define G_BH 18432
#define G_TOTAL 36864

__global__ __launch_bounds__(256, 2) void gemm_mma_kernel(
    const float* __restrict__ x, const float* __restrict__ bias) {
    extern __shared__ char smem[];
    const uint32_t sb = smem_u32(smem);
    const int tid = threadIdx.x;
    const int wid = tid >> 5, lane = tid & 31;
    const int g = lane >> 2, tg = lane & 3;
    const int mw = wid & 3, nw = wid >> 2;
    const int gm0 = blockIdx.y * 128;
    const int gn0 = blockIdx.x * 128;

    float acc[2][8][4];
#pragma unroll
    for (int mt = 0; mt < 2; ++mt)
#pragma unroll
        for (int nt = 0; nt < 8; ++nt)
#pragma unroll
            for (int e = 0; e < 4; ++e) acc[mt][nt][e] = 0.f;

    const int xm = tid >> 1, xh4 = (tid & 1) * 32;
    const uint32_t a_h_dst = sb + G_AH + xm * 144 + xh4 * 2;
    const int brow = tid >> 3, bseg = (tid & 7) * 8;

    for (int kc = 0; kc < 8; ++kc) {
#pragma unroll
        for (int it = 0; it < 4; ++it) {
            const int row = brow + it * 32;
            cp_async16(sb + G_BH + row * 144 + bseg * 2,
                       &g_Wh[(size_t)(gn0 + row) * WPITCH + kc * 64 + bseg]);
        }
        asm volatile("cp.async.commit_group;" ::: "memory");
        {
            const float4* xs = reinterpret_cast<const float4*>(
                x + (size_t)(gm0 + xm) * 512 + kc * 64 + xh4);
            unsigned short sh[32];
#pragma unroll
            for (int q = 0; q < 8; ++q) {
                float4 v = xs[q];
                sh[q * 4 + 0] = __half_as_ushort(__float2half(v.x));
                sh[q * 4 + 1] = __half_as_ushort(__float2half(v.y));
                sh[q * 4 + 2] = __half_as_ushort(__float2half(v.z));
                sh[q * 4 + 3] = __half_as_ushort(__float2half(v.w));
            }
#pragma unroll
            for (int q = 0; q < 4; ++q) {
                uint4 v;
                v.x = (uint32_t)sh[q * 8 + 0] | ((uint32_t)sh[q * 8 + 1] << 16);
                v.y = (uint32_t)sh[q * 8 + 2] | ((uint32_t)sh[q * 8 + 3] << 16);
                v.z = (uint32_t)sh[q * 8 + 4] | ((uint32_t)sh[q * 8 + 5] << 16);
                v.w = (uint32_t)sh[q * 8 + 6] | ((uint32_t)sh[q * 8 + 7] << 16);
                *reinterpret_cast<uint4*>(smem + (a_h_dst - sb) + q * 16) = v;
            }
        }
        asm volatile("cp.async.wait_group 0;" ::: "memory");
        __syncthreads();

        const uint32_t bb = sb + G_BH + (lane & 7) * 144 + ((lane >> 3) & 1) * 16 +
                            (nw * 64) * 144;
#pragma unroll
        for (int s = 0; s < 4; ++s) {
            uint32_t ah[2][4];
#pragma unroll
            for (int mt = 0; mt < 2; ++mt) {
                const int mr = mw * 32 + mt * 16;
                const uint32_t ra = (mr + g) * 144 + (s * 16 + tg * 2) * 2;
                const uint32_t rb = (mr + g + 8) * 144 + (s * 16 + tg * 2) * 2;
                ah[mt][0] = *reinterpret_cast<const uint32_t*>(smem + G_AH + ra);
                ah[mt][1] = *reinterpret_cast<const uint32_t*>(smem + G_AH + rb);
                ah[mt][2] = *reinterpret_cast<const uint32_t*>(smem + G_AH + ra + 16);
                ah[mt][3] = *reinterpret_cast<const uint32_t*>(smem + G_AH + rb + 16);
            }
#pragma unroll
            for (int nt = 0; nt < 8; ++nt) {
                uint32_t bh0, bh1;
                const uint32_t bo = bb + nt * 8 * 144 + s * 32;
                ldsm_x2(bh0, bh1, bo);
#pragma unroll
                for (int mt = 0; mt < 2; ++mt)
                    mma16816h(acc[mt][nt], ah[mt], bh0, bh1);
            }
        }
        __syncthreads();
    }
#pragma unroll
    for (int nt = 0; nt < 8; ++nt) {
        const int col = gn0 + nw * 64 + nt * 8 + tg * 2;
        const float b0 = __ldg(&bias[col]), b1 = __ldg(&bias[col + 1]);
#pragma unroll
        for (int mt = 0; mt < 2; ++mt) {
            const int row = gm0 + mw * 32 + mt * 16 + g;
            float2 v0 = {acc[mt][nt][0] + b0, acc[mt][nt][1] + b1};
            float2 v1 = {acc[mt][nt][2] + b0, acc[mt][nt][3] + b1};
            *reinterpret_cast<float2*>(&g_h[(size_t)row * 512 + col]) = v0;
            *reinterpret_cast<float2*>(&g_h[(size_t)(row + 8) * 512 + col]) = v1;
        }
    }
}

// ---------------------------------------------------------------------------
// K2: decayed scan — batched loads for MLP
// ---------------------------------------------------------------------------
__global__ void scan_local_kernel() {
    const int tid = blockIdx.x * blockDim.x + threadIdx.x;
    const int m = tid >> 12, c = tid & 4095;
    const int b = c >> 9, hd = c & 511;
    const float* hp = g_h + (size_t)(b * Tn + m * CHUNK) * En + hd;
    float s = 0.f;
    for (int t0 = 0; t0 < CHUNK; t0 += 8) {
        float buf[8];
#pragma unroll
        for (int u = 0; u < 8; ++u) buf[u] = hp[(size_t)(t0 + u) * En];
#pragma unroll
        for (int u = 0; u < 8; ++u) s = (s + buf[u]) * INV_DECAY;
    }
    g_local[m * NCH + c] = s;
}
__global__ void scan_emit_kernel() {
    const int tid = blockIdx.x * blockDim.x + threadIdx.x;
    const int m = tid >> 12, c = tid & 4095;
    const int b = c >> 9, hd = c & 511;
    float r = 1.f;
#pragma unroll
    for (int q = 0; q < CHUNK; ++q) r *= INV_DECAY;
    float s = 0.f;
    for (int mm = 0; mm < m; ++mm) s = s * r + g_local[mm * NCH + c];
    const float* hp = g_h + (size_t)(b * Tn + m * CHUNK) * En + hd;
    float* Sp = g_S + (size_t)(b * Tn + m * CHUNK) * En + hd;
    for (int t0 = 0; t0 < CHUNK; t0 += 8) {
        float buf[8], sv[8];
#pragma unroll
        for (int u = 0; u < 8; ++u) buf[u] = hp[(size_t)(t0 + u) * En];
#pragma unroll
        for (int u = 0; u < 8; ++u) {
            sv[u] = s;
            s = (s + buf[u]) * INV_DECAY;
        }
#pragma unroll
        for (int u = 0; u < 8; ++u) Sp[(size_t)(t0 + u) * En] = sv[u];
    }
}

// ---------------------------------------------------------------------------
// K3: bilinear via mma.sync fp16 (S single, C single) — R12 winner, unchanged
// ---------------------------------------------------------------------------
#define SM_A 0            // 256*80  = 20480
#define SM_B 20480        // 1024*80 = 81920
#define SM_Y 102400       // 256*33*4 = 33792
#define SM_TOTAL 136192

__global__ __launch_bounds__(256, 1) void bilinear_mma_kernel() {
    extern __shared__ char smem[];
    const uint32_t sb = smem_u32(smem);
    const int tid = threadIdx.x;
    const int wid = tid >> 5, lane = tid & 31;
    const int head = blockIdx.y;
    const int tok0 = blockIdx.x * 256;
    float* ys = reinterpret_cast<float*>(smem + SM_Y);

    // C prefetch FIRST (hidden behind A pack): 1024 rows x 80B = 5120 uint4
    {
        const uint4* gsrc = g_Cpack + (size_t)head * 5120;
#pragma unroll
        for (int t = 0; t < 20; ++t) {
            const int gidx = tid + t * 256;
            cp_async16(sb + SM_B + gidx * 16, gsrc + gidx);
        }
        asm volatile("cp.async.commit_group;" ::: "memory");
    }

    // A pack: each thread packs one of 256 rows (S -> fp16 single)
    {
        const int r = tid;
        const float* Sp = &g_S[(size_t)(tok0 + r) * 512 + head * 32];
        unsigned short sh[32];
#pragma unroll
        for (int q = 0; q < 8; ++q) {
            float4 v = *reinterpret_cast<const float4*>(Sp + q * 4);
            sh[q * 4 + 0] = __half_as_ushort(__float2half(v.x));
            sh[q * 4 + 1] = __half_as_ushort(__float2half(v.y));
            sh[q * 4 + 2] = __half_as_ushort(__float2half(v.z));
            sh[q * 4 + 3] = __half_as_ushort(__float2half(v.w));
        }
        uint4* arow = reinterpret_cast<uint4*>(smem + SM_A + r * 80);
#pragma unroll
        for (int q = 0; q < 4; ++q) {
            uint4 v;
            v.x = (uint32_t)sh[q * 8 + 0] | ((uint32_t)sh[q * 8 + 1] << 16);
            v.y = (uint32_t)sh[q * 8 + 2] | ((uint32_t)sh[q * 8 + 3] << 16);
            v.z = (uint32_t)sh[q * 8 + 4] | ((uint32_t)sh[q * 8 + 5] << 16);
            v.w = (uint32_t)sh[q * 8 + 6] | ((uint32_t)sh[q * 8 + 7] << 16);
            arow[q] = v;
        }
    }
    asm volatile("cp.async.wait_group 0;" ::: "memory");
    __syncthreads();

    {
        const int g = lane >> 2, tg = lane & 3;
        uint32_t afr[2][2][4];
        float hreg[2][4][4];
#pragma unroll
        for (int mt = 0; mt < 2; ++mt) {
            const int mr = (wid * 2 + mt) * 16;
#pragma unroll
            for (int s = 0; s < 2; ++s) {
                const char* base = smem + SM_A;
                const uint32_t ra = (mr + g) * 80 + s * 32 + tg * 4;
                const uint32_t rb = (mr + g + 8) * 80 + s * 32 + tg * 4;
                afr[mt][s][0] = *reinterpret_cast<const uint32_t*>(base + ra);
                afr[mt][s][1] = *reinterpret_cast<const uint32_t*>(base + rb);
                afr[mt][s][2] = *reinterpret_cast<const uint32_t*>(base + ra + 16);
                afr[mt][s][3] = *reinterpret_cast<const uint32_t*>(base + rb + 16);
            }
#pragma unroll
            for (int it = 0; it < 4; ++it) {
                const int i0 = it * 8 + tg * 2;
                float2 va = *reinterpret_cast<const float2*>(
                    &g_h[(size_t)(tok0 + mr + g) * 512 + head * 32 + i0]);
                float2 vb = *reinterpret_cast<const float2*>(
                    &g_h[(size_t)(tok0 + mr + g + 8) * 512 + head * 32 + i0]);
                hreg[mt][it][0] = va.x; hreg[mt][it][1] = va.y;
                hreg[mt][it][2] = vb.x; hreg[mt][it][3] = vb.y;
            }
        }
        const uint32_t bb4 = sb + SM_B + (lane & 7) * 80 + ((lane >> 3) & 3) * 16;

        for (int k = 0; k < 32; ++k) {
            float yA0 = 0.f, yB0 = 0.f, yA1 = 0.f, yB1 = 0.f;
#pragma unroll
            for (int it = 0; it < 4; ++it) {
                const uint32_t boff = bb4 + (uint32_t)(k * 32 + it * 8) * 80;
                uint32_t bh[4];
                ldsm_x4(bh, boff);
#pragma unroll
                for (int mt = 0; mt < 2; ++mt) {
                    float d[4] = {0.f, 0.f, 0.f, 0.f};
                    mma16816h(d, afr[mt][0], bh[0], bh[1]);   // S.C lo-j
                    mma16816h(d, afr[mt][1], bh[2], bh[3]);   // S.C hi-j
                    if (mt == 0) {
                        yA0 = fmaf(d[0], hreg[0][it][0], fmaf(d[1], hreg[0][it][1], yA0));
                        yB0 = fmaf(d[2], hreg[0][it][2], fmaf(d[3], hreg[0][it][3], yB0));
                    } else {
                        yA1 = fmaf(d[0], hreg[1][it][0], fmaf(d[1], hreg[1][it][1], yA1));
                        yB1 = fmaf(d[2], hreg[1][it][2], fmaf(d[3], hreg[1][it][3], yB1));
                    }
                }
            }
#pragma unroll
            for (int o = 1; o <= 2; o <<= 1) {
                yA0 += __shfl_xor_sync(0xffffffffu, yA0, o);
                yB0 += __shfl_xor_sync(0xffffffffu, yB0, o);
                yA1 += __shfl_xor_sync(0xffffffffu, yA1, o);
                yB1 += __shfl_xor_sync(0xffffffffu, yB1, o);
            }
            if (tg == (k & 3)) {
                const int mrA = (wid * 2) * 16, mrB = (wid * 2 + 1) * 16;
                ys[(mrA + g) * 33 + k] = yA0;
                ys[(mrA + g + 8) * 33 + k] = yB0;
                ys[(mrB + g) * 33 + k] = yA1;
                ys[(mrB + g + 8) * 33 + k] = yB1;
            }
        }
    }
    __syncthreads();

    // residual (re-read g_h from L2) + coalesced store
#pragma unroll
    for (int p = 0; p < 8; ++p) {
        const int idx = tid + p * 256;
        const int r = idx >> 3, c = (idx & 7) * 4;
        const float4 hv = *reinterpret_cast<const float4*>(
            &g_h[(size_t)(tok0 + r) * 512 + head * 32 + c]);
        float4 v;
        v.x = ys[r * 33 + c + 0] + hv.x;
        v.y = ys[r * 33 + c + 1] + hv.y;
        v.z = ys[r * 33 + c + 2] + hv.z;
        v.w = ys[r * 33 + c + 3] + hv.w;
        *reinterpret_cast<float4*>(
            &g_y[(size_t)(tok0 + r) * 512 + head * 32 + c]) = v;
    }
}

// ---------------------------------------------------------------------------
// K4: LayerNorm
// ---------------------------------------------------------------------------
__global__ __launch_bounds__(256) void ln_kernel(const float* __restrict__ gamma,
                                                 const float* __restrict__ beta,
                                                 float* __restrict__ out) {
    const int w = threadIdx.x >> 5, lane = threadIdx.x & 31;
    const int token = blockIdx.x * 8 + w;
    const float* yp = g_y + (size_t)token * En;
    float vals[16], sum = 0.f, sq = 0.f;
#pragma unroll
    for (int c2 = 0; c2 < 16; ++c2) {
        const float v = yp[c2 * 32 + lane];
        vals[c2] = v; sum += v; sq = fmaf(v, v, sq);
    }
#pragma unroll
    for (int o = 16; o; o >>= 1) {
        sum += __shfl_xor_sync(0xffffffffu, sum, o);
        sq += __shfl_xor_sync(0xffffffffu, sq, o);
    }
    const float mu = sum * (1.f / 512.f);
    const float var = sq * (1.f / 512.f) - mu * mu;
    const float inv = rsqrtf(var + LN_EPS);
    float* op = out + (size_t)token * En;
#pragma unroll
    for (int c2 = 0; c2 < 16; ++c2) {
        const int e = c2 * 32 + lane;
        op[e] = (vals[c2] - mu) * inv * gamma[e] + beta[e];
    }
}

// ---------------------------------------------------------------------------
extern "C" void kernel_launch(void* const* d_in, const int* in_sizes, int n_in,
                              void* d_out, int out_size) {
    const float* x = (const float*)d_in[0];
    const float* W = (const float*)d_in[1];
    const float* bias = (const float*)d_in[2];
    const float* cmap = (const float*)d_in[3];
    const float* gamma = (const float*)d_in[4];
    const float* beta = (const float*)d_in[5];
    float* out = (float*)d_out;

    static int smem_set = 0;
    if (!smem_set) {
        cudaFuncSetAttribute(bilinear_mma_kernel,
                             cudaFuncAttributeMaxDynamicSharedMemorySize, SM_TOTAL);
        cudaFuncSetAttribute(gemm_mma_kernel,
                             cudaFuncAttributeMaxDynamicSharedMemorySize, G_TOTAL);
        smem_set = 1;
    }

    cpack_kernel<<<64, 256>>>(cmap);
    wpack_kernel<<<128, 256>>>(W);
    gemm_mma_kernel<<<dim3(4, 128), 256, G_TOTAL>>>(x, bias);
    scan_local_kernel<<<NCHUNK * NCH / 256, 256>>>();
    scan_emit_kernel<<<NCHUNK * NCH / 256, 256>>>();
    bilinear_mma_kernel<<<dim3(64, Hn), 256, SM_TOTAL>>>();
    ln_kernel<<<BT / 8, 256>>>(gamma, beta, out);
}

// round 14
// speedup vs baseline: 1.9389x; 1.1497x over previous
#include <cuda_runtime.h>
#include <cuda_bf16.h>
#include <cuda_fp16.h>
#include <cstdint>

// ConceptLayer: h = xW+b ; S = decayed scan ; y = bilinear(h,S;C)+h ; LayerNorm
// B=8 T=2048 E=512 H=16 D=32.  sm_100-safe: mma.sync (HMMA), cp.async, ldmatrix.
#define Bn 8
#define Tn 2048
#define En 512
#define Hn 16
#define BT (Bn * Tn)
#define LN_EPS 1e-3f
#define INV_DECAY (1.0f / 1.2f)
#define CHUNK 128
#define NCHUNK (Tn / CHUNK)
#define NCH (Bn * En)
#define WPITCH 520

__device__ float g_h[BT * En];
__device__ __half g_S16[BT * En];     // S stored fp16 (same rounding point as pack)
__device__ float g_y[BT * En];
__device__ float g_local[NCHUNK * NCH];
// C packed fp16: [head][n=k*32+i][40 fp16 pitch] (80B rows)
__device__ uint4 g_Cpack[Hn * 1024 * 5];
// W packed transposed fp16: [n][k] pitch 520
__device__ __half g_Wh[512 * WPITCH];

__device__ __forceinline__ uint32_t smem_u32(const void* p) {
    uint32_t a;
    asm("{ .reg .u64 t; cvta.to.shared.u64 t, %1; cvt.u32.u64 %0, t; }" : "=r"(a) : "l"(p));
    return a;
}
__device__ __forceinline__ void mma16816h(float* d, const uint32_t* a, uint32_t b0, uint32_t b1) {
    asm volatile(
        "mma.sync.aligned.m16n8k16.row.col.f32.f16.f16.f32 "
        "{%0,%1,%2,%3}, {%4,%5,%6,%7}, {%8,%9}, {%0,%1,%2,%3};"
        : "+f"(d[0]), "+f"(d[1]), "+f"(d[2]), "+f"(d[3])
        : "r"(a[0]), "r"(a[1]), "r"(a[2]), "r"(a[3]), "r"(b0), "r"(b1));
}
__device__ __forceinline__ void ldsm_x2(uint32_t& r0, uint32_t& r1, uint32_t addr) {
    asm volatile("ldmatrix.sync.aligned.m8n8.x2.shared.b16 {%0,%1}, [%2];"
                 : "=r"(r0), "=r"(r1) : "r"(addr));
}
__device__ __forceinline__ void ldsm_x4(uint32_t* r, uint32_t addr) {
    asm volatile("ldmatrix.sync.aligned.m8n8.x4.shared.b16 {%0,%1,%2,%3}, [%4];"
                 : "=r"(r[0]), "=r"(r[1]), "=r"(r[2]), "=r"(r[3]) : "r"(addr));
}
__device__ __forceinline__ void cp_async16(uint32_t dst, const void* src) {
    asm volatile("cp.async.cg.shared.global [%0], [%1], 16;" :: "r"(dst), "l"(src) : "memory");
}

// ---------------------------------------------------------------------------
// K0a: pack C -> fp16 [head][n][40] (single level, 80B pitch)
// ---------------------------------------------------------------------------
__global__ void cpack_kernel(const float* __restrict__ C) {
    const int idx = blockIdx.x * 256 + threadIdx.x;
    const float* src = C + (size_t)idx * 32;
    unsigned short hi[32];
#pragma unroll
    for (int j = 0; j < 32; ++j) hi[j] = __half_as_ushort(__float2half(src[j]));
    uint4* dst = g_Cpack + (size_t)idx * 5;
#pragma unroll
    for (int q = 0; q < 4; ++q) {
        uint4 v;
        v.x = (uint32_t)hi[q * 8 + 0] | ((uint32_t)hi[q * 8 + 1] << 16);
        v.y = (uint32_t)hi[q * 8 + 2] | ((uint32_t)hi[q * 8 + 3] << 16);
        v.z = (uint32_t)hi[q * 8 + 4] | ((uint32_t)hi[q * 8 + 5] << 16);
        v.w = (uint32_t)hi[q * 8 + 6] | ((uint32_t)hi[q * 8 + 7] << 16);
        dst[q] = v;
    }
    dst[4] = make_uint4(0u, 0u, 0u, 0u);
}

// ---------------------------------------------------------------------------
// K0b: pack W [k][n] f32 -> g_Wh [n][k] fp16, pitch WPITCH
// ---------------------------------------------------------------------------
__global__ void wpack_kernel(const float* __restrict__ W) {
    const int n = (blockIdx.x & 1) * 256 + threadIdx.x;
    const int k0 = (blockIdx.x >> 1) * 8;
    unsigned short hi[8];
#pragma unroll
    for (int u = 0; u < 8; ++u)
        hi[u] = __half_as_ushort(__float2half(W[(size_t)(k0 + u) * 512 + n]));
    uint4 vh;
    vh.x = (uint32_t)hi[0] | ((uint32_t)hi[1] << 16);
    vh.y = (uint32_t)hi[2] | ((uint32_t)hi[3] << 16);
    vh.z = (uint32_t)hi[4] | ((uint32_t)hi[5] << 16);
    vh.w = (uint32_t)hi[6] | ((uint32_t)hi[7] << 16);
    *reinterpret_cast<uint4*>(&g_Wh[(size_t)n * WPITCH + k0]) = vh;
}

// ---------------------------------------------------------------------------
// K1: h = x @ W + b via mma.sync fp16 (R13 winner, unchanged)
// ---------------------------------------------------------------------------
#define G_AH 0
#define G_BH 18432
#define G_TOTAL 36864

__global__ __launch_bounds__(256, 2) void gemm_mma_kernel(
    const float* __restrict__ x, const float* __restrict__ bias) {
    extern __shared__ char smem[];
    const uint32_t sb = smem_u32(smem);
    const int tid = threadIdx.x;
    const int wid = tid >> 5, lane = tid & 31;
    const int g = lane >> 2, tg = lane & 3;
    const int mw = wid & 3, nw = wid >> 2;
    const int gm0 = blockIdx.y * 128;
    const int gn0 = blockIdx.x * 128;

    float acc[2][8][4];
#pragma unroll
    for (int mt = 0; mt < 2; ++mt)
#pragma unroll
        for (int nt = 0; nt < 8; ++nt)
#pragma unroll
            for (int e = 0; e < 4; ++e) acc[mt][nt][e] = 0.f;

    const int xm = tid >> 1, xh4 = (tid & 1) * 32;
    const uint32_t a_h_dst = sb + G_AH + xm * 144 + xh4 * 2;
    const int brow = tid >> 3, bseg = (tid & 7) * 8;

    for (int kc = 0; kc < 8; ++kc) {
#pragma unroll
        for (int it = 0; it < 4; ++it) {
            const int row = brow + it * 32;
            cp_async16(sb + G_BH + row * 144 + bseg * 2,
                       &g_Wh[(size_t)(gn0 + row) * WPITCH + kc * 64 + bseg]);
        }
        asm volatile("cp.async.commit_group;" ::: "memory");
        {
            const float4* xs = reinterpret_cast<const float4*>(
                x + (size_t)(gm0 + xm) * 512 + kc * 64 + xh4);
            unsigned short sh[32];
#pragma unroll
            for (int q = 0; q < 8; ++q) {
                float4 v = xs[q];
                sh[q * 4 + 0] = __half_as_ushort(__float2half(v.x));
                sh[q * 4 + 1] = __half_as_ushort(__float2half(v.y));
                sh[q * 4 + 2] = __half_as_ushort(__float2half(v.z));
                sh[q * 4 + 3] = __half_as_ushort(__float2half(v.w));
            }
#pragma unroll
            for (int q = 0; q < 4; ++q) {
                uint4 v;
                v.x = (uint32_t)sh[q * 8 + 0] | ((uint32_t)sh[q * 8 + 1] << 16);
                v.y = (uint32_t)sh[q * 8 + 2] | ((uint32_t)sh[q * 8 + 3] << 16);
                v.z = (uint32_t)sh[q * 8 + 4] | ((uint32_t)sh[q * 8 + 5] << 16);
                v.w = (uint32_t)sh[q * 8 + 6] | ((uint32_t)sh[q * 8 + 7] << 16);
                *reinterpret_cast<uint4*>(smem + (a_h_dst - sb) + q * 16) = v;
            }
        }
        asm volatile("cp.async.wait_group 0;" ::: "memory");
        __syncthreads();

        const uint32_t bb = sb + G_BH + (lane & 7) * 144 + ((lane >> 3) & 1) * 16 +
                            (nw * 64) * 144;
#pragma unroll
        for (int s = 0; s < 4; ++s) {
            uint32_t ah[2][4];
#pragma unroll
            for (int mt = 0; mt < 2; ++mt) {
                const int mr = mw * 32 + mt * 16;
                const uint32_t ra = (mr + g) * 144 + (s * 16 + tg * 2) * 2;
                const uint32_t rb = (mr + g + 8) * 144 + (s * 16 + tg * 2) * 2;
                ah[mt][0] = *reinterpret_cast<const uint32_t*>(smem + G_AH + ra);
                ah[mt][1] = *reinterpret_cast<const uint32_t*>(smem + G_AH + rb);
                ah[mt][2] = *reinterpret_cast<const uint32_t*>(smem + G_AH + ra + 16);
                ah[mt][3] = *reinterpret_cast<const uint32_t*>(smem + G_AH + rb + 16);
            }
#pragma unroll
            for (int nt = 0; nt < 8; ++nt) {
                uint32_t bh0, bh1;
                const uint32_t bo = bb + nt * 8 * 144 + s * 32;
                ldsm_x2(bh0, bh1, bo);
#pragma unroll
                for (int mt = 0; mt < 2; ++mt)
                    mma16816h(acc[mt][nt], ah[mt], bh0, bh1);
            }
        }
        __syncthreads();
    }
#pragma unroll
    for (int nt = 0; nt < 8; ++nt) {
        const int col = gn0 + nw * 64 + nt * 8 + tg * 2;
        const float b0 = __ldg(&bias[col]), b1 = __ldg(&bias[col + 1]);
#pragma unroll
        for (int mt = 0; mt < 2; ++mt) {
            const int row = gm0 + mw * 32 + mt * 16 + g;
            float2 v0 = {acc[mt][nt][0] + b0, acc[mt][nt][1] + b1};
            float2 v1 = {acc[mt][nt][2] + b0, acc[mt][nt][3] + b1};
            *reinterpret_cast<float2*>(&g_h[(size_t)row * 512 + col]) = v0;
            *reinterpret_cast<float2*>(&g_h[(size_t)(row + 8) * 512 + col]) = v1;
        }
    }
}

// ---------------------------------------------------------------------------
// K2: decayed scan — batched loads for MLP; S written fp16
// ---------------------------------------------------------------------------
__global__ void scan_local_kernel() {
    const int tid = blockIdx.x * blockDim.x + threadIdx.x;
    const int m = tid >> 12, c = tid & 4095;
    const int b = c >> 9, hd = c & 511;
    const float* hp = g_h + (size_t)(b * Tn + m * CHUNK) * En + hd;
    float s = 0.f;
    for (int t0 = 0; t0 < CHUNK; t0 += 8) {
        float buf[8];
#pragma unroll
        for (int u = 0; u < 8; ++u) buf[u] = hp[(size_t)(t0 + u) * En];
#pragma unroll
        for (int u = 0; u < 8; ++u) s = (s + buf[u]) * INV_DECAY;
    }
    g_local[m * NCH + c] = s;
}
__global__ void scan_emit_kernel() {
    const int tid = blockIdx.x * blockDim.x + threadIdx.x;
    const int m = tid >> 12, c = tid & 4095;
    const int b = c >> 9, hd = c & 511;
    float r = 1.f;
#pragma unroll
    for (int q = 0; q < CHUNK; ++q) r *= INV_DECAY;
    float s = 0.f;
    for (int mm = 0; mm < m; ++mm) s = s * r + g_local[mm * NCH + c];
    const float* hp = g_h + (size_t)(b * Tn + m * CHUNK) * En + hd;
    __half* Sp = g_S16 + (size_t)(b * Tn + m * CHUNK) * En + hd;
    for (int t0 = 0; t0 < CHUNK; t0 += 8) {
        float buf[8], sv[8];
#pragma unroll
        for (int u = 0; u < 8; ++u) buf[u] = hp[(size_t)(t0 + u) * En];
#pragma unroll
        for (int u = 0; u < 8; ++u) {
            sv[u] = s;
            s = (s + buf[u]) * INV_DECAY;
        }
#pragma unroll
        for (int u = 0; u < 8; ++u) Sp[(size_t)(t0 + u) * En] = __float2half(sv[u]);
    }
}

// ---------------------------------------------------------------------------
// K3: bilinear via mma.sync fp16 — C in 2 halves (512 rows / 40KB each) for
// 2 CTAs/SM; A is a pure fp16 copy from g_S16.
// ---------------------------------------------------------------------------
#define SM_A 0            // 256*80  = 20480
#define SM_B 20480        // 512*80  = 40960
#define SM_Y 61440        // 256*33*4 = 33792
#define SM_TOTAL 95232

__global__ __launch_bounds__(256, 2) void bilinear_mma_kernel() {
    extern __shared__ char smem[];
    const uint32_t sb = smem_u32(smem);
    const int tid = threadIdx.x;
    const int wid = tid >> 5, lane = tid & 31;
    const int head = blockIdx.y;
    const int tok0 = blockIdx.x * 256;
    float* ys = reinterpret_cast<float*>(smem + SM_Y);
    const uint4* gsrc = g_Cpack + (size_t)head * 5120;

    // C chunk 0 prefetch (rows 0-511, k=0..15), hidden behind A pack
    {
#pragma unroll
        for (int t = 0; t < 10; ++t) {
            const int gidx = tid + t * 256;
            cp_async16(sb + SM_B + gidx * 16, gsrc + gidx);
        }
        asm volatile("cp.async.commit_group;" ::: "memory");
    }

    // A pack: pure copy of fp16 S rows
    {
        const int r = tid;
        const uint4* s4 = reinterpret_cast<const uint4*>(
            &g_S16[(size_t)(tok0 + r) * 512 + head * 32]);
        uint4* arow = reinterpret_cast<uint4*>(smem + SM_A + r * 80);
#pragma unroll
        for (int q = 0; q < 4; ++q) arow[q] = s4[q];
    }
    asm volatile("cp.async.wait_group 0;" ::: "memory");
    __syncthreads();

    const int g = lane >> 2, tg = lane & 3;
    uint32_t afr[2][2][4];
    float hreg[2][4][4];
#pragma unroll
    for (int mt = 0; mt < 2; ++mt) {
        const int mr = (wid * 2 + mt) * 16;
#pragma unroll
        for (int s = 0; s < 2; ++s) {
            const char* base = smem + SM_A;
            const uint32_t ra = (mr + g) * 80 + s * 32 + tg * 4;
            const uint32_t rb = (mr + g + 8) * 80 + s * 32 + tg * 4;
            afr[mt][s][0] = *reinterpret_cast<const uint32_t*>(base + ra);
            afr[mt][s][1] = *reinterpret_cast<const uint32_t*>(base + rb);
            afr[mt][s][2] = *reinterpret_cast<const uint32_t*>(base + ra + 16);
            afr[mt][s][3] = *reinterpret_cast<const uint32_t*>(base + rb + 16);
        }
#pragma unroll
        for (int it = 0; it < 4; ++it) {
            const int i0 = it * 8 + tg * 2;
            float2 va = *reinterpret_cast<const float2*>(
                &g_h[(size_t)(tok0 + mr + g) * 512 + head * 32 + i0]);
            float2 vb = *reinterpret_cast<const float2*>(
                &g_h[(size_t)(tok0 + mr + g + 8) * 512 + head * 32 + i0]);
            hreg[mt][it][0] = va.x; hreg[mt][it][1] = va.y;
            hreg[mt][it][2] = vb.x; hreg[mt][it][3] = vb.y;
        }
    }
    const uint32_t bb4 = sb + SM_B + (lane & 7) * 80 + ((lane >> 3) & 3) * 16;

#pragma unroll 1
    for (int kh = 0; kh < 2; ++kh) {
        for (int k = kh * 16; k < kh * 16 + 16; ++k) {
            float yA0 = 0.f, yB0 = 0.f, yA1 = 0.f, yB1 = 0.f;
#pragma unroll
            for (int it = 0; it < 4; ++it) {
                const uint32_t boff =
                    bb4 + (uint32_t)((k - kh * 16) * 32 + it * 8) * 80;
                uint32_t bh[4];
                ldsm_x4(bh, boff);
#pragma unroll
                for (int mt = 0; mt < 2; ++mt) {
                    float d[4] = {0.f, 0.f, 0.f, 0.f};
                    mma16816h(d, afr[mt][0], bh[0], bh[1]);
                    mma16816h(d, afr[mt][1], bh[2], bh[3]);
                    if (mt == 0) {
                        yA0 = fmaf(d[0], hreg[0][it][0], fmaf(d[1], hreg[0][it][1], yA0));
                        yB0 = fmaf(d[2], hreg[0][it][2], fmaf(d[3], hreg[0][it][3], yB0));
                    } else {
                        yA1 = fmaf(d[0], hreg[1][it][0], fmaf(d[1], hreg[1][it][1], yA1));
                        yB1 = fmaf(d[2], hreg[1][it][2], fmaf(d[3], hreg[1][it][3], yB1));
                    }
                }
            }
#pragma unroll
            for (int o = 1; o <= 2; o <<= 1) {
                yA0 += __shfl_xor_sync(0xffffffffu, yA0, o);
                yB0 += __shfl_xor_sync(0xffffffffu, yB0, o);
                yA1 += __shfl_xor_sync(0xffffffffu, yA1, o);
                yB1 += __shfl_xor_sync(0xffffffffu, yB1, o);
            }
            if (tg == (k & 3)) {
                const int mrA = (wid * 2) * 16, mrB = (wid * 2 + 1) * 16;
                ys[(mrA + g) * 33 + k] = yA0;
                ys[(mrA + g + 8) * 33 + k] = yB0;
                ys[(mrB + g) * 33 + k] = yA1;
                ys[(mrB + g + 8) * 33 + k] = yB1;
            }
        }
        if (kh == 0) {
            __syncthreads();    // all reads of C chunk 0 done
#pragma unroll
            for (int t = 0; t < 10; ++t) {
                const int gidx = tid + t * 256;
                cp_async16(sb + SM_B + gidx * 16, gsrc + 2560 + gidx);
            }
            asm volatile("cp.async.commit_group;" ::: "memory");
            asm volatile("cp.async.wait_group 0;" ::: "memory");
            __syncthreads();
        }
    }
    __syncthreads();

    // residual (re-read g_h from L2) + coalesced store
#pragma unroll
    for (int p = 0; p < 8; ++p) {
        const int idx = tid + p * 256;
        const int r = idx >> 3, c = (idx & 7) * 4;
        const float4 hv = *reinterpret_cast<const float4*>(
            &g_h[(size_t)(tok0 + r) * 512 + head * 32 + c]);
        float4 v;
        v.x = ys[r * 33 + c + 0] + hv.x;
        v.y = ys[r * 33 + c + 1] + hv.y;
        v.z = ys[r * 33 + c + 2] + hv.z;
        v.w = ys[r * 33 + c + 3] + hv.w;
        *reinterpret_cast<float4*>(
            &g_y[(size_t)(tok0 + r) * 512 + head * 32 + c]) = v;
    }
}

// ---------------------------------------------------------------------------
// K4: LayerNorm
// ---------------------------------------------------------------------------
__global__ __launch_bounds__(256) void ln_kernel(const float* __restrict__ gamma,
                                                 const float* __restrict__ beta,
                                                 float* __restrict__ out) {
    const int w = threadIdx.x >> 5, lane = threadIdx.x & 31;
    const int token = blockIdx.x * 8 + w;
    const float* yp = g_y + (size_t)token * En;
    float vals[16], sum = 0.f, sq = 0.f;
#pragma unroll
    for (int c2 = 0; c2 < 16; ++c2) {
        const float v = yp[c2 * 32 + lane];
        vals[c2] = v; sum += v; sq = fmaf(v, v, sq);
    }
#pragma unroll
    for (int o = 16; o; o >>= 1) {
        sum += __shfl_xor_sync(0xffffffffu, sum, o);
        sq += __shfl_xor_sync(0xffffffffu, sq, o);
    }
    const float mu = sum * (1.f / 512.f);
    const float var = sq * (1.f / 512.f) - mu * mu;
    const float inv = rsqrtf(var + LN_EPS);
    float* op = out + (size_t)token * En;
#pragma unroll
    for (int c2 = 0; c2 < 16; ++c2) {
        const int e = c2 * 32 + lane;
        op[e] = (vals[c2] - mu) * inv * gamma[e] + beta[e];
    }
}

// ---------------------------------------------------------------------------
extern "C" void kernel_launch(void* const* d_in, const int* in_sizes, int n_in,
                              void* d_out, int out_size) {
    const float* x = (const float*)d_in[0];
    const float* W = (const float*)d_in[1];
    const float* bias = (const float*)d_in[2];
    const float* cmap = (const float*)d_in[3];
    const float* gamma = (const float*)d_in[4];
    const float* beta = (const float*)d_in[5];
    float* out = (float*)d_out;

    static int smem_set = 0;
    if (!smem_set) {
        cudaFuncSetAttribute(bilinear_mma_kernel,
                             cudaFuncAttributeMaxDynamicSharedMemorySize, SM_TOTAL);
        cudaFuncSetAttribute(gemm_mma_kernel,
                             cudaFuncAttributeMaxDynamicSharedMemorySize, G_TOTAL);
        smem_set = 1;
    }

    cpack_kernel<<<64, 256>>>(cmap);
    wpack_kernel<<<128, 256>>>(W);
    gemm_mma_kernel<<<dim3(4, 128), 256, G_TOTAL>>>(x, bias);
    scan_local_kernel<<<NCHUNK * NCH / 256, 256>>>();
    scan_emit_kernel<<<NCHUNK * NCH / 256, 256>>>();
    bilinear_mma_kernel<<<dim3(64, Hn), 256, SM_TOTAL>>>();
    ln_kernel<<<BT / 8, 256>>>(gamma, beta, out);
}

// round 15
// speedup vs baseline: 2.0128x; 1.0381x over previous
#include <cuda_runtime.h>
#include <cuda_bf16.h>
#include <cuda_fp16.h>
#include <cstdint>

// ConceptLayer: h = xW+b ; S = decayed scan ; y = bilinear(h,S;C)+h ; LayerNorm
// B=8 T=2048 E=512 H=16 D=32.  sm_100-safe: mma.sync (HMMA), cp.async, ldmatrix.
#define Bn 8
#define Tn 2048
#define En 512
#define Hn 16
#define BT (Bn * Tn)
#define LN_EPS 1e-3f
#define INV_DECAY (1.0f / 1.2f)
#define CHUNK 128
#define NCHUNK (Tn / CHUNK)
#define NCH (Bn * En)
#define WPITCH 520

__device__ __half g_h16[BT * En];     // h stored fp16 (sole copy)
__device__ __half g_S16[BT * En];     // S stored fp16
__device__ float g_y[BT * En];
__device__ float g_local[NCHUNK * NCH];
// C packed fp16: [head][n=k*32+i][40 fp16 pitch] (80B rows)
__device__ uint4 g_Cpack[Hn * 1024 * 5];
// W packed transposed fp16: [n][k] pitch 520
__device__ __half g_Wh[512 * WPITCH];

__device__ __forceinline__ uint32_t smem_u32(const void* p) {
    uint32_t a;
    asm("{ .reg .u64 t; cvta.to.shared.u64 t, %1; cvt.u32.u64 %0, t; }" : "=r"(a) : "l"(p));
    return a;
}
__device__ __forceinline__ void mma16816h(float* d, const uint32_t* a, uint32_t b0, uint32_t b1) {
    asm volatile(
        "mma.sync.aligned.m16n8k16.row.col.f32.f16.f16.f32 "
        "{%0,%1,%2,%3}, {%4,%5,%6,%7}, {%8,%9}, {%0,%1,%2,%3};"
        : "+f"(d[0]), "+f"(d[1]), "+f"(d[2]), "+f"(d[3])
        : "r"(a[0]), "r"(a[1]), "r"(a[2]), "r"(a[3]), "r"(b0), "r"(b1));
}
__device__ __forceinline__ void ldsm_x2(uint32_t& r0, uint32_t& r1, uint32_t addr) {
    asm volatile("ldmatrix.sync.aligned.m8n8.x2.shared.b16 {%0,%1}, [%2];"
                 : "=r"(r0), "=r"(r1) : "r"(addr));
}
__device__ __forceinline__ void ldsm_x4(uint32_t* r, uint32_t addr) {
    asm volatile("ldmatrix.sync.aligned.m8n8.x4.shared.b16 {%0,%1,%2,%3}, [%4];"
                 : "=r"(r[0]), "=r"(r[1]), "=r"(r[2]), "=r"(r[3]) : "r"(addr));
}
__device__ __forceinline__ void cp_async16(uint32_t dst, const void* src) {
    asm volatile("cp.async.cg.shared.global [%0], [%1], 16;" :: "r"(dst), "l"(src) : "memory");
}

// ---------------------------------------------------------------------------
// K0a: pack C -> fp16 [head][n][40] (single level, 80B pitch)
// ---------------------------------------------------------------------------
__global__ void cpack_kernel(const float* __restrict__ C) {
    const int idx = blockIdx.x * 256 + threadIdx.x;
    const float* src = C + (size_t)idx * 32;
    unsigned short hi[32];
#pragma unroll
    for (int j = 0; j < 32; ++j) hi[j] = __half_as_ushort(__float2half(src[j]));
    uint4* dst = g_Cpack + (size_t)idx * 5;
#pragma unroll
    for (int q = 0; q < 4; ++q) {
        uint4 v;
        v.x = (uint32_t)hi[q * 8 + 0] | ((uint32_t)hi[q * 8 + 1] << 16);
        v.y = (uint32_t)hi[q * 8 + 2] | ((uint32_t)hi[q * 8 + 3] << 16);
        v.z = (uint32_t)hi[q * 8 + 4] | ((uint32_t)hi[q * 8 + 5] << 16);
        v.w = (uint32_t)hi[q * 8 + 6] | ((uint32_t)hi[q * 8 + 7] << 16);
        dst[q] = v;
    }
    dst[4] = make_uint4(0u, 0u, 0u, 0u);
}

// ---------------------------------------------------------------------------
// K0b: pack W [k][n] f32 -> g_Wh [n][k] fp16, pitch WPITCH
// ---------------------------------------------------------------------------
__global__ void wpack_kernel(const float* __restrict__ W) {
    const int n = (blockIdx.x & 1) * 256 + threadIdx.x;
    const int k0 = (blockIdx.x >> 1) * 8;
    unsigned short hi[8];
#pragma unroll
    for (int u = 0; u < 8; ++u)
        hi[u] = __half_as_ushort(__float2half(W[(size_t)(k0 + u) * 512 + n]));
    uint4 vh;
    vh.x = (uint32_t)hi[0] | ((uint32_t)hi[1] << 16);
    vh.y = (uint32_t)hi[2] | ((uint32_t)hi[3] << 16);
    vh.z = (uint32_t)hi[4] | ((uint32_t)hi[5] << 16);
    vh.w = (uint32_t)hi[6] | ((uint32_t)hi[7] << 16);
    *reinterpret_cast<uint4*>(&g_Wh[(size_t)n * WPITCH + k0]) = vh;
}

// ---------------------------------------------------------------------------
// K1: h = x @ W + b via mma.sync fp16; epilogue stores h as fp16
// ---------------------------------------------------------------------------
#define G_AH 0
#define G_BH 18432
#define G_TOTAL 36864

__global__ __launch_bounds__(256, 2) void gemm_mma_kernel(
    const float* __restrict__ x, const float* __restrict__ bias) {
    extern __shared__ char smem[];
    const uint32_t sb = smem_u32(smem);
    const int tid = threadIdx.x;
    const int wid = tid >> 5, lane = tid & 31;
    const int g = lane >> 2, tg = lane & 3;
    const int mw = wid & 3, nw = wid >> 2;
    const int gm0 = blockIdx.y * 128;
    const int gn0 = blockIdx.x * 128;

    float acc[2][8][4];
#pragma unroll
    for (int mt = 0; mt < 2; ++mt)
#pragma unroll
        for (int nt = 0; nt < 8; ++nt)
#pragma unroll
            for (int e = 0; e < 4; ++e) acc[mt][nt][e] = 0.f;

    const int xm = tid >> 1, xh4 = (tid & 1) * 32;
    const uint32_t a_h_dst = sb + G_AH + xm * 144 + xh4 * 2;
    const int brow = tid >> 3, bseg = (tid & 7) * 8;

    for (int kc = 0; kc < 8; ++kc) {
#pragma unroll
        for (int it = 0; it < 4; ++it) {
            const int row = brow + it * 32;
            cp_async16(sb + G_BH + row * 144 + bseg * 2,
                       &g_Wh[(size_t)(gn0 + row) * WPITCH + kc * 64 + bseg]);
        }
        asm volatile("cp.async.commit_group;" ::: "memory");
        {
            const float4* xs = reinterpret_cast<const float4*>(
                x + (size_t)(gm0 + xm) * 512 + kc * 64 + xh4);
            unsigned short sh[32];
#pragma unroll
            for (int q = 0; q < 8; ++q) {
                float4 v = xs[q];
                sh[q * 4 + 0] = __half_as_ushort(__float2half(v.x));
                sh[q * 4 + 1] = __half_as_ushort(__float2half(v.y));
                sh[q * 4 + 2] = __half_as_ushort(__float2half(v.z));
                sh[q * 4 + 3] = __half_as_ushort(__float2half(v.w));
            }
#pragma unroll
            for (int q = 0; q < 4; ++q) {
                uint4 v;
                v.x = (uint32_t)sh[q * 8 + 0] | ((uint32_t)sh[q * 8 + 1] << 16);
                v.y = (uint32_t)sh[q * 8 + 2] | ((uint32_t)sh[q * 8 + 3] << 16);
                v.z = (uint32_t)sh[q * 8 + 4] | ((uint32_t)sh[q * 8 + 5] << 16);
                v.w = (uint32_t)sh[q * 8 + 6] | ((uint32_t)sh[q * 8 + 7] << 16);
                *reinterpret_cast<uint4*>(smem + (a_h_dst - sb) + q * 16) = v;
            }
        }
        asm volatile("cp.async.wait_group 0;" ::: "memory");
        __syncthreads();

        const uint32_t bb = sb + G_BH + (lane & 7) * 144 + ((lane >> 3) & 1) * 16 +
                            (nw * 64) * 144;
#pragma unroll
        for (int s = 0; s < 4; ++s) {
            uint32_t ah[2][4];
#pragma unroll
            for (int mt = 0; mt < 2; ++mt) {
                const int mr = mw * 32 + mt * 16;
                const uint32_t ra = (mr + g) * 144 + (s * 16 + tg * 2) * 2;
                const uint32_t rb = (mr + g + 8) * 144 + (s * 16 + tg * 2) * 2;
                ah[mt][0] = *reinterpret_cast<const uint32_t*>(smem + G_AH + ra);
                ah[mt][1] = *reinterpret_cast<const uint32_t*>(smem + G_AH + rb);
                ah[mt][2] = *reinterpret_cast<const uint32_t*>(smem + G_AH + ra + 16);
                ah[mt][3] = *reinterpret_cast<const uint32_t*>(smem + G_AH + rb + 16);
            }
#pragma unroll
            for (int nt = 0; nt < 8; ++nt) {
                uint32_t bh0, bh1;
                const uint32_t bo = bb + nt * 8 * 144 + s * 32;
                ldsm_x2(bh0, bh1, bo);
#pragma unroll
                for (int mt = 0; mt < 2; ++mt)
                    mma16816h(acc[mt][nt], ah[mt], bh0, bh1);
            }
        }
        __syncthreads();
    }
#pragma unroll
    for (int nt = 0; nt < 8; ++nt) {
        const int col = gn0 + nw * 64 + nt * 8 + tg * 2;
        const float b0 = __ldg(&bias[col]), b1 = __ldg(&bias[col + 1]);
#pragma unroll
        for (int mt = 0; mt < 2; ++mt) {
            const int row = gm0 + mw * 32 + mt * 16 + g;
            *reinterpret_cast<__half2*>(&g_h16[(size_t)row * 512 + col]) =
                __floats2half2_rn(acc[mt][nt][0] + b0, acc[mt][nt][1] + b1);
            *reinterpret_cast<__half2*>(&g_h16[(size_t)(row + 8) * 512 + col]) =
                __floats2half2_rn(acc[mt][nt][2] + b0, acc[mt][nt][3] + b1);
        }
    }
}

// ---------------------------------------------------------------------------
// K2: decayed scan — fp16 h in, fp32 arithmetic, fp16 S out
// ---------------------------------------------------------------------------
__global__ void scan_local_kernel() {
    const int tid = blockIdx.x * blockDim.x + threadIdx.x;
    const int m = tid >> 12, c = tid & 4095;
    const int b = c >> 9, hd = c & 511;
    const __half* hp = g_h16 + (size_t)(b * Tn + m * CHUNK) * En + hd;
    float s = 0.f;
    for (int t0 = 0; t0 < CHUNK; t0 += 8) {
        float buf[8];
#pragma unroll
        for (int u = 0; u < 8; ++u) buf[u] = __half2float(hp[(size_t)(t0 + u) * En]);
#pragma unroll
        for (int u = 0; u < 8; ++u) s = (s + buf[u]) * INV_DECAY;
    }
    g_local[m * NCH + c] = s;
}
__global__ void scan_emit_kernel() {
    const int tid = blockIdx.x * blockDim.x + threadIdx.x;
    const int m = tid >> 12, c = tid & 4095;
    const int b = c >> 9, hd = c & 511;
    float r = 1.f;
#pragma unroll
    for (int q = 0; q < CHUNK; ++q) r *= INV_DECAY;
    float s = 0.f;
    for (int mm = 0; mm < m; ++mm) s = s * r + g_local[mm * NCH + c];
    const __half* hp = g_h16 + (size_t)(b * Tn + m * CHUNK) * En + hd;
    __half* Sp = g_S16 + (size_t)(b * Tn + m * CHUNK) * En + hd;
    for (int t0 = 0; t0 < CHUNK; t0 += 8) {
        float buf[8], sv[8];
#pragma unroll
        for (int u = 0; u < 8; ++u) buf[u] = __half2float(hp[(size_t)(t0 + u) * En]);
#pragma unroll
        for (int u = 0; u < 8; ++u) {
            sv[u] = s;
            s = (s + buf[u]) * INV_DECAY;
        }
#pragma unroll
        for (int u = 0; u < 8; ++u) Sp[(size_t)(t0 + u) * En] = __float2half(sv[u]);
    }
}

// ---------------------------------------------------------------------------
// K3: bilinear via mma.sync fp16 — C in 2 halves (40KB each), 2 CTAs/SM;
// h read fp16 from g_h16.
// ---------------------------------------------------------------------------
#define SM_A 0            // 256*80  = 20480
#define SM_B 20480        // 512*80  = 40960
#define SM_Y 61440        // 256*33*4 = 33792
#define SM_TOTAL 95232

__global__ __launch_bounds__(256, 2) void bilinear_mma_kernel() {
    extern __shared__ char smem[];
    const uint32_t sb = smem_u32(smem);
    const int tid = threadIdx.x;
    const int wid = tid >> 5, lane = tid & 31;
    const int head = blockIdx.y;
    const int tok0 = blockIdx.x * 256;
    float* ys = reinterpret_cast<float*>(smem + SM_Y);
    const uint4* gsrc = g_Cpack + (size_t)head * 5120;

    // C chunk 0 prefetch (rows 0-511, k=0..15), hidden behind A pack
    {
#pragma unroll
        for (int t = 0; t < 10; ++t) {
            const int gidx = tid + t * 256;
            cp_async16(sb + SM_B + gidx * 16, gsrc + gidx);
        }
        asm volatile("cp.async.commit_group;" ::: "memory");
    }

    // A pack: pure copy of fp16 S rows
    {
        const int r = tid;
        const uint4* s4 = reinterpret_cast<const uint4*>(
            &g_S16[(size_t)(tok0 + r) * 512 + head * 32]);
        uint4* arow = reinterpret_cast<uint4*>(smem + SM_A + r * 80);
#pragma unroll
        for (int q = 0; q < 4; ++q) arow[q] = s4[q];
    }
    asm volatile("cp.async.wait_group 0;" ::: "memory");
    __syncthreads();

    const int g = lane >> 2, tg = lane & 3;
    uint32_t afr[2][2][4];
    float hreg[2][4][4];
#pragma unroll
    for (int mt = 0; mt < 2; ++mt) {
        const int mr = (wid * 2 + mt) * 16;
#pragma unroll
        for (int s = 0; s < 2; ++s) {
            const char* base = smem + SM_A;
            const uint32_t ra = (mr + g) * 80 + s * 32 + tg * 4;
            const uint32_t rb = (mr + g + 8) * 80 + s * 32 + tg * 4;
            afr[mt][s][0] = *reinterpret_cast<const uint32_t*>(base + ra);
            afr[mt][s][1] = *reinterpret_cast<const uint32_t*>(base + rb);
            afr[mt][s][2] = *reinterpret_cast<const uint32_t*>(base + ra + 16);
            afr[mt][s][3] = *reinterpret_cast<const uint32_t*>(base + rb + 16);
        }
#pragma unroll
        for (int it = 0; it < 4; ++it) {
            const int i0 = it * 8 + tg * 2;
            float2 va = __half22float2(*reinterpret_cast<const __half2*>(
                &g_h16[(size_t)(tok0 + mr + g) * 512 + head * 32 + i0]));
            float2 vb = __half22float2(*reinterpret_cast<const __half2*>(
                &g_h16[(size_t)(tok0 + mr + g + 8) * 512 + head * 32 + i0]));
            hreg[mt][it][0] = va.x; hreg[mt][it][1] = va.y;
            hreg[mt][it][2] = vb.x; hreg[mt][it][3] = vb.y;
        }
    }
    const uint32_t bb4 = sb + SM_B + (lane & 7) * 80 + ((lane >> 3) & 3) * 16;

#pragma unroll 1
    for (int kh = 0; kh < 2; ++kh) {
        for (int k = kh * 16; k < kh * 16 + 16; ++k) {
            float yA0 = 0.f, yB0 = 0.f, yA1 = 0.f, yB1 = 0.f;
#pragma unroll
            for (int it = 0; it < 4; ++it) {
                const uint32_t boff =
                    bb4 + (uint32_t)((k - kh * 16) * 32 + it * 8) * 80;
                uint32_t bh[4];
                ldsm_x4(bh, boff);
#pragma unroll
                for (int mt = 0; mt < 2; ++mt) {
                    float d[4] = {0.f, 0.f, 0.f, 0.f};
                    mma16816h(d, afr[mt][0], bh[0], bh[1]);
                    mma16816h(d, afr[mt][1], bh[2], bh[3]);
                    if (mt == 0) {
                        yA0 = fmaf(d[0], hreg[0][it][0], fmaf(d[1], hreg[0][it][1], yA0));
                        yB0 = fmaf(d[2], hreg[0][it][2], fmaf(d[3], hreg[0][it][3], yB0));
                    } else {
                        yA1 = fmaf(d[0], hreg[1][it][0], fmaf(d[1], hreg[1][it][1], yA1));
                        yB1 = fmaf(d[2], hreg[1][it][2], fmaf(d[3], hreg[1][it][3], yB1));
                    }
                }
            }
#pragma unroll
            for (int o = 1; o <= 2; o <<= 1) {
                yA0 += __shfl_xor_sync(0xffffffffu, yA0, o);
                yB0 += __shfl_xor_sync(0xffffffffu, yB0, o);
                yA1 += __shfl_xor_sync(0xffffffffu, yA1, o);
                yB1 += __shfl_xor_sync(0xffffffffu, yB1, o);
            }
            if (tg == (k & 3)) {
                const int mrA = (wid * 2) * 16, mrB = (wid * 2 + 1) * 16;
                ys[(mrA + g) * 33 + k] = yA0;
                ys[(mrA + g + 8) * 33 + k] = yB0;
                ys[(mrB + g) * 33 + k] = yA1;
                ys[(mrB + g + 8) * 33 + k] = yB1;
            }
        }
        if (kh == 0) {
            __syncthreads();    // all reads of C chunk 0 done
#pragma unroll
            for (int t = 0; t < 10; ++t) {
                const int gidx = tid + t * 256;
                cp_async16(sb + SM_B + gidx * 16, gsrc + 2560 + gidx);
            }
            asm volatile("cp.async.commit_group;" ::: "memory");
            asm volatile("cp.async.wait_group 0;" ::: "memory");
            __syncthreads();
        }
    }
    __syncthreads();

    // residual (fp16 h) + coalesced store
#pragma unroll
    for (int p = 0; p < 8; ++p) {
        const int idx = tid + p * 256;
        const int r = idx >> 3, c = (idx & 7) * 4;
        const __half2* hp2 = reinterpret_cast<const __half2*>(
            &g_h16[(size_t)(tok0 + r) * 512 + head * 32 + c]);
        const float2 h01 = __half22float2(hp2[0]);
        const float2 h23 = __half22float2(hp2[1]);
        float4 v;
        v.x = ys[r * 33 + c + 0] + h01.x;
        v.y = ys[r * 33 + c + 1] + h01.y;
        v.z = ys[r * 33 + c + 2] + h23.x;
        v.w = ys[r * 33 + c + 3] + h23.y;
        *reinterpret_cast<float4*>(
            &g_y[(size_t)(tok0 + r) * 512 + head * 32 + c]) = v;
    }
}

// ---------------------------------------------------------------------------
// K4: LayerNorm
// ---------------------------------------------------------------------------
__global__ __launch_bounds__(256) void ln_kernel(const float* __restrict__ gamma,
                                                 const float* __restrict__ beta,
                                                 float* __restrict__ out) {
    const int w = threadIdx.x >> 5, lane = threadIdx.x & 31;
    const int token = blockIdx.x * 8 + w;
    const float* yp = g_y + (size_t)token * En;
    float vals[16], sum = 0.f, sq = 0.f;
#pragma unroll
    for (int c2 = 0; c2 < 16; ++c2) {
        const float v = yp[c2 * 32 + lane];
        vals[c2] = v; sum += v; sq = fmaf(v, v, sq);
    }
#pragma unroll
    for (int o = 16; o; o >>= 1) {
        sum += __shfl_xor_sync(0xffffffffu, sum, o);
        sq += __shfl_xor_sync(0xffffffffu, sq, o);
    }
    const float mu = sum * (1.f / 512.f);
    const float var = sq * (1.f / 512.f) - mu * mu;
    const float inv = rsqrtf(var + LN_EPS);
    float* op = out + (size_t)token * En;
#pragma unroll
    for (int c2 = 0; c2 < 16; ++c2) {
        const int e = c2 * 32 + lane;
        op[e] = (vals[c2] - mu) * inv * gamma[e] + beta[e];
    }
}

// ---------------------------------------------------------------------------
extern "C" void kernel_launch(void* const* d_in, const int* in_sizes, int n_in,
                              void* d_out, int out_size) {
    const float* x = (const float*)d_in[0];
    const float* W = (const float*)d_in[1];
    const float* bias = (const float*)d_in[2];
    const float* cmap = (const float*)d_in[3];
    const float* gamma = (const float*)d_in[4];
    const float* beta = (const float*)d_in[5];
    float* out = (float*)d_out;

    static int smem_set = 0;
    if (!smem_set) {
        cudaFuncSetAttribute(bilinear_mma_kernel,
                             cudaFuncAttributeMaxDynamicSharedMemorySize, SM_TOTAL);
        cudaFuncSetAttribute(gemm_mma_kernel,
                             cudaFuncAttributeMaxDynamicSharedMemorySize, G_TOTAL);
        smem_set = 1;
    }

    cpack_kernel<<<64, 256>>>(cmap);
    wpack_kernel<<<128, 256>>>(W);
    gemm_mma_kernel<<<dim3(4, 128), 256, G_TOTAL>>>(x, bias);
    scan_local_kernel<<<NCHUNK * NCH / 256, 256>>>();
    scan_emit_kernel<<<NCHUNK * NCH / 256, 256>>>();
    bilinear_mma_kernel<<<dim3(64, Hn), 256, SM_TOTAL>>>();
    ln_kernel<<<BT / 8, 256>>>(gamma, beta, out);
}

// round 16
// speedup vs baseline: 2.0473x; 1.0171x over previous
#include <cuda_runtime.h>
#include <cuda_bf16.h>
#include <cuda_fp16.h>
#include <cstdint>

// ConceptLayer: h = xW+b ; S = decayed scan ; y = bilinear(h,S;C)+h ; LayerNorm
// B=8 T=2048 E=512 H=16 D=32.  sm_100-safe: mma.sync (HMMA), cp.async, ldmatrix.
#define Bn 8
#define Tn 2048
#define En 512
#define Hn 16
#define BT (Bn * Tn)
#define LN_EPS 1e-3f
#define INV_DECAY (1.0f / 1.2f)
#define CHUNK 64
#define NCHUNK (Tn / CHUNK)     // 32
#define NCH (Bn * En)
#define WPITCH 520

__device__ __half g_h16[BT * En];     // h stored fp16 (sole copy)
__device__ __half g_S16[BT * En];     // S stored fp16
__device__ __half g_y16[BT * En];     // pre-LN y stored fp16
__device__ float g_local[NCHUNK * NCH];
// C packed fp16: [head][n=k*32+i][40 fp16 pitch] (80B rows)
__device__ uint4 g_Cpack[Hn * 1024 * 5];
// W packed transposed fp16: [n][k] pitch 520
__device__ __half g_Wh[512 * WPITCH];

__device__ __forceinline__ uint32_t smem_u32(const void* p) {
    uint32_t a;
    asm("{ .reg .u64 t; cvta.to.shared.u64 t, %1; cvt.u32.u64 %0, t; }" : "=r"(a) : "l"(p));
    return a;
}
__device__ __forceinline__ void mma16816h(float* d, const uint32_t* a, uint32_t b0, uint32_t b1) {
    asm volatile(
        "mma.sync.aligned.m16n8k16.row.col.f32.f16.f16.f32 "
        "{%0,%1,%2,%3}, {%4,%5,%6,%7}, {%8,%9}, {%0,%1,%2,%3};"
        : "+f"(d[0]), "+f"(d[1]), "+f"(d[2]), "+f"(d[3])
        : "r"(a[0]), "r"(a[1]), "r"(a[2]), "r"(a[3]), "r"(b0), "r"(b1));
}
__device__ __forceinline__ void ldsm_x2(uint32_t& r0, uint32_t& r1, uint32_t addr) {
    asm volatile("ldmatrix.sync.aligned.m8n8.x2.shared.b16 {%0,%1}, [%2];"
                 : "=r"(r0), "=r"(r1) : "r"(addr));
}
__device__ __forceinline__ void ldsm_x4(uint32_t* r, uint32_t addr) {
    asm volatile("ldmatrix.sync.aligned.m8n8.x4.shared.b16 {%0,%1,%2,%3}, [%4];"
                 : "=r"(r[0]), "=r"(r[1]), "=r"(r[2]), "=r"(r[3]) : "r"(addr));
}
__device__ __forceinline__ void cp_async16(uint32_t dst, const void* src) {
    asm volatile("cp.async.cg.shared.global [%0], [%1], 16;" :: "r"(dst), "l"(src) : "memory");
}

// ---------------------------------------------------------------------------
// K0a: pack C -> fp16 [head][n][40] (single level, 80B pitch)
// ---------------------------------------------------------------------------
__global__ void cpack_kernel(const float* __restrict__ C) {
    const int idx = blockIdx.x * 256 + threadIdx.x;
    const float* src = C + (size_t)idx * 32;
    unsigned short hi[32];
#pragma unroll
    for (int j = 0; j < 32; ++j) hi[j] = __half_as_ushort(__float2half(src[j]));
    uint4* dst = g_Cpack + (size_t)idx * 5;
#pragma unroll
    for (int q = 0; q < 4; ++q) {
        uint4 v;
        v.x = (uint32_t)hi[q * 8 + 0] | ((uint32_t)hi[q * 8 + 1] << 16);
        v.y = (uint32_t)hi[q * 8 + 2] | ((uint32_t)hi[q * 8 + 3] << 16);
        v.z = (uint32_t)hi[q * 8 + 4] | ((uint32_t)hi[q * 8 + 5] << 16);
        v.w = (uint32_t)hi[q * 8 + 6] | ((uint32_t)hi[q * 8 + 7] << 16);
        dst[q] = v;
    }
    dst[4] = make_uint4(0u, 0u, 0u, 0u);
}

// ---------------------------------------------------------------------------
// K0b: pack W [k][n] f32 -> g_Wh [n][k] fp16, pitch WPITCH
// ---------------------------------------------------------------------------
__global__ void wpack_kernel(const float* __restrict__ W) {
    const int n = (blockIdx.x & 1) * 256 + threadIdx.x;
    const int k0 = (blockIdx.x >> 1) * 8;
    unsigned short hi[8];
#pragma unroll
    for (int u = 0; u < 8; ++u)
        hi[u] = __half_as_ushort(__float2half(W[(size_t)(k0 + u) * 512 + n]));
    uint4 vh;
    vh.x = (uint32_t)hi[0] | ((uint32_t)hi[1] << 16);
    vh.y = (uint32_t)hi[2] | ((uint32_t)hi[3] << 16);
    vh.z = (uint32_t)hi[4] | ((uint32_t)hi[5] << 16);
    vh.w = (uint32_t)hi[6] | ((uint32_t)hi[7] << 16);
    *reinterpret_cast<uint4*>(&g_Wh[(size_t)n * WPITCH + k0]) = vh;
}

// ---------------------------------------------------------------------------
// K1: h = x @ W + b via mma.sync fp16; epilogue stores h as fp16
// ---------------------------------------------------------------------------
#define G_AH 0
#define G_BH 18432
#define G_TOTAL 36864

__global__ __launch_bounds__(256, 2) void gemm_mma_kernel(
    const float* __restrict__ x, const float* __restrict__ bias) {
    extern __shared__ char smem[];
    const uint32_t sb = smem_u32(smem);
    const int tid = threadIdx.x;
    const int wid = tid >> 5, lane = tid & 31;
    const int g = lane >> 2, tg = lane & 3;
    const int mw = wid & 3, nw = wid >> 2;
    const int gm0 = blockIdx.y * 128;
    const int gn0 = blockIdx.x * 128;

    float acc[2][8][4];
#pragma unroll
    for (int mt = 0; mt < 2; ++mt)
#pragma unroll
        for (int nt = 0; nt < 8; ++nt)
#pragma unroll
            for (int e = 0; e < 4; ++e) acc[mt][nt][e] = 0.f;

    const int xm = tid >> 1, xh4 = (tid & 1) * 32;
    const uint32_t a_h_dst = sb + G_AH + xm * 144 + xh4 * 2;
    const int brow = tid >> 3, bseg = (tid & 7) * 8;

    for (int kc = 0; kc < 8; ++kc) {
#pragma unroll
        for (int it = 0; it < 4; ++it) {
            const int row = brow + it * 32;
            cp_async16(sb + G_BH + row * 144 + bseg * 2,
                       &g_Wh[(size_t)(gn0 + row) * WPITCH + kc * 64 + bseg]);
        }
        asm volatile("cp.async.commit_group;" ::: "memory");
        {
            const float4* xs = reinterpret_cast<const float4*>(
                x + (size_t)(gm0 + xm) * 512 + kc * 64 + xh4);
            unsigned short sh[32];
#pragma unroll
            for (int q = 0; q < 8; ++q) {
                float4 v = xs[q];
                sh[q * 4 + 0] = __half_as_ushort(__float2half(v.x));
                sh[q * 4 + 1] = __half_as_ushort(__float2half(v.y));
                sh[q * 4 + 2] = __half_as_ushort(__float2half(v.z));
                sh[q * 4 + 3] = __half_as_ushort(__float2half(v.w));
            }
#pragma unroll
            for (int q = 0; q < 4; ++q) {
                uint4 v;
                v.x = (uint32_t)sh[q * 8 + 0] | ((uint32_t)sh[q * 8 + 1] << 16);
                v.y = (uint32_t)sh[q * 8 + 2] | ((uint32_t)sh[q * 8 + 3] << 16);
                v.z = (uint32_t)sh[q * 8 + 4] | ((uint32_t)sh[q * 8 + 5] << 16);
                v.w = (uint32_t)sh[q * 8 + 6] | ((uint32_t)sh[q * 8 + 7] << 16);
                *reinterpret_cast<uint4*>(smem + (a_h_dst - sb) + q * 16) = v;
            }
        }
        asm volatile("cp.async.wait_group 0;" ::: "memory");
        __syncthreads();

        const uint32_t bb = sb + G_BH + (lane & 7) * 144 + ((lane >> 3) & 1) * 16 +
                            (nw * 64) * 144;
#pragma unroll
        for (int s = 0; s < 4; ++s) {
            uint32_t ah[2][4];
#pragma unroll
            for (int mt = 0; mt < 2; ++mt) {
                const int mr = mw * 32 + mt * 16;
                const uint32_t ra = (mr + g) * 144 + (s * 16 + tg * 2) * 2;
                const uint32_t rb = (mr + g + 8) * 144 + (s * 16 + tg * 2) * 2;
                ah[mt][0] = *reinterpret_cast<const uint32_t*>(smem + G_AH + ra);
                ah[mt][1] = *reinterpret_cast<const uint32_t*>(smem + G_AH + rb);
                ah[mt][2] = *reinterpret_cast<const uint32_t*>(smem + G_AH + ra + 16);
                ah[mt][3] = *reinterpret_cast<const uint32_t*>(smem + G_AH + rb + 16);
            }
#pragma unroll
            for (int nt = 0; nt < 8; ++nt) {
                uint32_t bh0, bh1;
                const uint32_t bo = bb + nt * 8 * 144 + s * 32;
                ldsm_x2(bh0, bh1, bo);
#pragma unroll
                for (int mt = 0; mt < 2; ++mt)
                    mma16816h(acc[mt][nt], ah[mt], bh0, bh1);
            }
        }
        __syncthreads();
    }
#pragma unroll
    for (int nt = 0; nt < 8; ++nt) {
        const int col = gn0 + nw * 64 + nt * 8 + tg * 2;
        const float b0 = __ldg(&bias[col]), b1 = __ldg(&bias[col + 1]);
#pragma unroll
        for (int mt = 0; mt < 2; ++mt) {
            const int row = gm0 + mw * 32 + mt * 16 + g;
            *reinterpret_cast<__half2*>(&g_h16[(size_t)row * 512 + col]) =
                __floats2half2_rn(acc[mt][nt][0] + b0, acc[mt][nt][1] + b1);
            *reinterpret_cast<__half2*>(&g_h16[(size_t)(row + 8) * 512 + col]) =
                __floats2half2_rn(acc[mt][nt][2] + b0, acc[mt][nt][3] + b1);
        }
    }
}

// ---------------------------------------------------------------------------
// K2: decayed scan — CHUNK=64 (2x parallelism), fp16 in/out, fp32 math
// ---------------------------------------------------------------------------
__global__ void scan_local_kernel() {
    const int tid = blockIdx.x * blockDim.x + threadIdx.x;
    const int m = tid >> 12, c = tid & 4095;
    const int b = c >> 9, hd = c & 511;
    const __half* hp = g_h16 + (size_t)(b * Tn + m * CHUNK) * En + hd;
    float s = 0.f;
    for (int t0 = 0; t0 < CHUNK; t0 += 8) {
        float buf[8];
#pragma unroll
        for (int u = 0; u < 8; ++u) buf[u] = __half2float(hp[(size_t)(t0 + u) * En]);
#pragma unroll
        for (int u = 0; u < 8; ++u) s = (s + buf[u]) * INV_DECAY;
    }
    g_local[m * NCH + c] = s;
}
__global__ void scan_emit_kernel() {
    const int tid = blockIdx.x * blockDim.x + threadIdx.x;
    const int m = tid >> 12, c = tid & 4095;
    const int b = c >> 9, hd = c & 511;
    float r = 1.f;
#pragma unroll
    for (int q = 0; q < CHUNK; ++q) r *= INV_DECAY;  // (1/1.2)^64
    float s = 0.f;
    for (int mm = 0; mm < m; ++mm) s = s * r + g_local[mm * NCH + c];
    const __half* hp = g_h16 + (size_t)(b * Tn + m * CHUNK) * En + hd;
    __half* Sp = g_S16 + (size_t)(b * Tn + m * CHUNK) * En + hd;
    for (int t0 = 0; t0 < CHUNK; t0 += 8) {
        float buf[8], sv[8];
#pragma unroll
        for (int u = 0; u < 8; ++u) buf[u] = __half2float(hp[(size_t)(t0 + u) * En]);
#pragma unroll
        for (int u = 0; u < 8; ++u) {
            sv[u] = s;
            s = (s + buf[u]) * INV_DECAY;
        }
#pragma unroll
        for (int u = 0; u < 8; ++u) Sp[(size_t)(t0 + u) * En] = __float2half(sv[u]);
    }
}

// ---------------------------------------------------------------------------
// K3: bilinear via mma.sync fp16 — C in 2 halves (40KB each), 2 CTAs/SM;
// h fp16, y stored fp16.
// ---------------------------------------------------------------------------
#define SM_A 0            // 256*80  = 20480
#define SM_B 20480        // 512*80  = 40960
#define SM_Y 61440        // 256*33*4 = 33792
#define SM_TOTAL 95232

__global__ __launch_bounds__(256, 2) void bilinear_mma_kernel() {
    extern __shared__ char smem[];
    const uint32_t sb = smem_u32(smem);
    const int tid = threadIdx.x;
    const int wid = tid >> 5, lane = tid & 31;
    const int head = blockIdx.y;
    const int tok0 = blockIdx.x * 256;
    float* ys = reinterpret_cast<float*>(smem + SM_Y);
    const uint4* gsrc = g_Cpack + (size_t)head * 5120;

    // C chunk 0 prefetch (rows 0-511, k=0..15), hidden behind A pack
    {
#pragma unroll
        for (int t = 0; t < 10; ++t) {
            const int gidx = tid + t * 256;
            cp_async16(sb + SM_B + gidx * 16, gsrc + gidx);
        }
        asm volatile("cp.async.commit_group;" ::: "memory");
    }

    // A pack: pure copy of fp16 S rows
    {
        const int r = tid;
        const uint4* s4 = reinterpret_cast<const uint4*>(
            &g_S16[(size_t)(tok0 + r) * 512 + head * 32]);
        uint4* arow = reinterpret_cast<uint4*>(smem + SM_A + r * 80);
#pragma unroll
        for (int q = 0; q < 4; ++q) arow[q] = s4[q];
    }
    asm volatile("cp.async.wait_group 0;" ::: "memory");
    __syncthreads();

    const int g = lane >> 2, tg = lane & 3;
    uint32_t afr[2][2][4];
    float hreg[2][4][4];
#pragma unroll
    for (int mt = 0; mt < 2; ++mt) {
        const int mr = (wid * 2 + mt) * 16;
#pragma unroll
        for (int s = 0; s < 2; ++s) {
            const char* base = smem + SM_A;
            const uint32_t ra = (mr + g) * 80 + s * 32 + tg * 4;
            const uint32_t rb = (mr + g + 8) * 80 + s * 32 + tg * 4;
            afr[mt][s][0] = *reinterpret_cast<const uint32_t*>(base + ra);
            afr[mt][s][1] = *reinterpret_cast<const uint32_t*>(base + rb);
            afr[mt][s][2] = *reinterpret_cast<const uint32_t*>(base + ra + 16);
            afr[mt][s][3] = *reinterpret_cast<const uint32_t*>(base + rb + 16);
        }
#pragma unroll
        for (int it = 0; it < 4; ++it) {
            const int i0 = it * 8 + tg * 2;
            float2 va = __half22float2(*reinterpret_cast<const __half2*>(
                &g_h16[(size_t)(tok0 + mr + g) * 512 + head * 32 + i0]));
            float2 vb = __half22float2(*reinterpret_cast<const __half2*>(
                &g_h16[(size_t)(tok0 + mr + g + 8) * 512 + head * 32 + i0]));
            hreg[mt][it][0] = va.x; hreg[mt][it][1] = va.y;
            hreg[mt][it][2] = vb.x; hreg[mt][it][3] = vb.y;
        }
    }
    const uint32_t bb4 = sb + SM_B + (lane & 7) * 80 + ((lane >> 3) & 3) * 16;

#pragma unroll 1
    for (int kh = 0; kh < 2; ++kh) {
        for (int k = kh * 16; k < kh * 16 + 16; ++k) {
            float yA0 = 0.f, yB0 = 0.f, yA1 = 0.f, yB1 = 0.f;
#pragma unroll
            for (int it = 0; it < 4; ++it) {
                const uint32_t boff =
                    bb4 + (uint32_t)((k - kh * 16) * 32 + it * 8) * 80;
                uint32_t bh[4];
                ldsm_x4(bh, boff);
#pragma unroll
                for (int mt = 0; mt < 2; ++mt) {
                    float d[4] = {0.f, 0.f, 0.f, 0.f};
                    mma16816h(d, afr[mt][0], bh[0], bh[1]);
                    mma16816h(d, afr[mt][1], bh[2], bh[3]);
                    if (mt == 0) {
                        yA0 = fmaf(d[0], hreg[0][it][0], fmaf(d[1], hreg[0][it][1], yA0));
                        yB0 = fmaf(d[2], hreg[0][it][2], fmaf(d[3], hreg[0][it][3], yB0));
                    } else {
                        yA1 = fmaf(d[0], hreg[1][it][0], fmaf(d[1], hreg[1][it][1], yA1));
                        yB1 = fmaf(d[2], hreg[1][it][2], fmaf(d[3], hreg[1][it][3], yB1));
                    }
                }
            }
#pragma unroll
            for (int o = 1; o <= 2; o <<= 1) {
                yA0 += __shfl_xor_sync(0xffffffffu, yA0, o);
                yB0 += __shfl_xor_sync(0xffffffffu, yB0, o);
                yA1 += __shfl_xor_sync(0xffffffffu, yA1, o);
                yB1 += __shfl_xor_sync(0xffffffffu, yB1, o);
            }
            if (tg == (k & 3)) {
                const int mrA = (wid * 2) * 16, mrB = (wid * 2 + 1) * 16;
                ys[(mrA + g) * 33 + k] = yA0;
                ys[(mrA + g + 8) * 33 + k] = yB0;
                ys[(mrB + g) * 33 + k] = yA1;
                ys[(mrB + g + 8) * 33 + k] = yB1;
            }
        }
        if (kh == 0) {
            __syncthreads();    // all reads of C chunk 0 done
#pragma unroll
            for (int t = 0; t < 10; ++t) {
                const int gidx = tid + t * 256;
                cp_async16(sb + SM_B + gidx * 16, gsrc + 2560 + gidx);
            }
            asm volatile("cp.async.commit_group;" ::: "memory");
            asm volatile("cp.async.wait_group 0;" ::: "memory");
            __syncthreads();
        }
    }
    __syncthreads();

    // residual (fp16 h) + coalesced fp16 store of y
#pragma unroll
    for (int p = 0; p < 8; ++p) {
        const int idx = tid + p * 256;
        const int r = idx >> 3, c = (idx & 7) * 4;
        const __half2* hp2 = reinterpret_cast<const __half2*>(
            &g_h16[(size_t)(tok0 + r) * 512 + head * 32 + c]);
        const float2 h01 = __half22float2(hp2[0]);
        const float2 h23 = __half22float2(hp2[1]);
        __half2* yp2 = reinterpret_cast<__half2*>(
            &g_y16[(size_t)(tok0 + r) * 512 + head * 32 + c]);
        yp2[0] = __floats2half2_rn(ys[r * 33 + c + 0] + h01.x,
                                   ys[r * 33 + c + 1] + h01.y);
        yp2[1] = __floats2half2_rn(ys[r * 33 + c + 2] + h23.x,
                                   ys[r * 33 + c + 3] + h23.y);
    }
}

// ---------------------------------------------------------------------------
// K4: LayerNorm (fp16 y in, fp32 out)
// ---------------------------------------------------------------------------
__global__ __launch_bounds__(256) void ln_kernel(const float* __restrict__ gamma,
                                                 const float* __restrict__ beta,
                                                 float* __restrict__ out) {
    const int w = threadIdx.x >> 5, lane = threadIdx.x & 31;
    const int token = blockIdx.x * 8 + w;
    const __half* yp = g_y16 + (size_t)token * En;
    float vals[16], sum = 0.f, sq = 0.f;
#pragma unroll
    for (int c2 = 0; c2 < 16; ++c2) {
        const float v = __half2float(yp[c2 * 32 + lane]);
        vals[c2] = v; sum += v; sq = fmaf(v, v, sq);
    }
#pragma unroll
    for (int o = 16; o; o >>= 1) {
        sum += __shfl_xor_sync(0xffffffffu, sum, o);
        sq += __shfl_xor_sync(0xffffffffu, sq, o);
    }
    const float mu = sum * (1.f / 512.f);
    const float var = sq * (1.f / 512.f) - mu * mu;
    const float inv = rsqrtf(var + LN_EPS);
    float* op = out + (size_t)token * En;
#pragma unroll
    for (int c2 = 0; c2 < 16; ++c2) {
        const int e = c2 * 32 + lane;
        op[e] = (vals[c2] - mu) * inv * gamma[e] + beta[e];
    }
}

// ---------------------------------------------------------------------------
extern "C" void kernel_launch(void* const* d_in, const int* in_sizes, int n_in,
                              void* d_out, int out_size) {
    const float* x = (const float*)d_in[0];
    const float* W = (const float*)d_in[1];
    const float* bias = (const float*)d_in[2];
    const float* cmap = (const float*)d_in[3];
    const float* gamma = (const float*)d_in[4];
    const float* beta = (const float*)d_in[5];
    float* out = (float*)d_out;

    static int smem_set = 0;
    if (!smem_set) {
        cudaFuncSetAttribute(bilinear_mma_kernel,
                             cudaFuncAttributeMaxDynamicSharedMemorySize, SM_TOTAL);
        cudaFuncSetAttribute(gemm_mma_kernel,
                             cudaFuncAttributeMaxDynamicSharedMemorySize, G_TOTAL);
        smem_set = 1;
    }

    cpack_kernel<<<64, 256>>>(cmap);
    wpack_kernel<<<128, 256>>>(W);
    gemm_mma_kernel<<<dim3(4, 128), 256, G_TOTAL>>>(x, bias);
    scan_local_kernel<<<NCHUNK * NCH / 256, 256>>>();
    scan_emit_kernel<<<NCHUNK * NCH / 256, 256>>>();
    bilinear_mma_kernel<<<dim3(64, Hn), 256, SM_TOTAL>>>();
    ln_kernel<<<BT / 8, 256>>>(gamma, beta, out);
}